// round 5
// baseline (speedup 1.0000x reference)
#include <cuda_runtime.h>
#include <cuda_bf16.h>
#include <math.h>
#include <stdint.h>

// ---------------- problem constants ----------------
namespace cfg {
constexpr int B = 2, T = 2048, D = 1024, H = 16, HD = 64, F = 4096, V = 32000;
constexpr int M = B * T;
constexpr float EPS = 1e-6f;
}

// ---------------- scratch ----------------------------------------------------
__device__ float g_h[cfg::M * cfg::D];
__device__ float g_q[cfg::M * cfg::D];
__device__ float g_k[cfg::M * cfg::D];
__device__ float g_v[cfg::M * cfg::D];
__device__ float g_o[cfg::M * cfg::D];
__device__ float g_f[(size_t)cfg::M * cfg::F];

// int8 two-level quant buffers
__device__ int8_t g_a1[(size_t)cfg::M * cfg::F];
__device__ int8_t g_a2[(size_t)cfg::M * cfg::F];
__device__ float  g_as[cfg::M];
__device__ int8_t g_wq1[(size_t)cfg::V * cfg::D];
__device__ int8_t g_wq2[(size_t)cfg::V * cfg::D];
__device__ float  g_ws[cfg::V];

// ---------------- PTX helpers -------------------------------------------------
__device__ __forceinline__ uint32_t smem_u32(const void* p) {
    uint32_t a;
    asm("{ .reg .u64 t; cvta.to.shared.u64 t, %1; cvt.u32.u64 %0, t; }" : "=r"(a) : "l"(p));
    return a;
}
__device__ __forceinline__ void cp16(uint32_t dst, const void* src) {
    asm volatile("cp.async.cg.shared.global [%0], [%1], 16;" :: "r"(dst), "l"(src));
}
__device__ __forceinline__ void cp_commit() {
    asm volatile("cp.async.commit_group;" ::: "memory");
}
template <int N>
__device__ __forceinline__ void cp_wait() {
    asm volatile("cp.async.wait_group %0;" :: "n"(N) : "memory");
}
__device__ __forceinline__ void ldmat4(uint32_t* r, uint32_t addr) {
    asm volatile("ldmatrix.sync.aligned.m8n8.x4.shared.b16 {%0,%1,%2,%3}, [%4];"
                 : "=r"(r[0]), "=r"(r[1]), "=r"(r[2]), "=r"(r[3]) : "r"(addr));
}
__device__ __forceinline__ void ldmat2(uint32_t* r, uint32_t addr) {
    asm volatile("ldmatrix.sync.aligned.m8n8.x2.shared.b16 {%0,%1}, [%2];"
                 : "=r"(r[0]), "=r"(r[1]) : "r"(addr));
}
__device__ __forceinline__ void mma16816(float* c, const uint32_t* a, uint32_t b0, uint32_t b1) {
    asm volatile(
        "mma.sync.aligned.m16n8k16.row.col.f32.bf16.bf16.f32 "
        "{%0,%1,%2,%3}, {%4,%5,%6,%7}, {%8,%9}, {%0,%1,%2,%3};"
        : "+f"(c[0]), "+f"(c[1]), "+f"(c[2]), "+f"(c[3])
        : "r"(a[0]), "r"(a[1]), "r"(a[2]), "r"(a[3]), "r"(b0), "r"(b1));
}
__device__ __forceinline__ void imma16832(int* c, const uint32_t* a, uint32_t b0, uint32_t b1) {
    asm volatile(
        "mma.sync.aligned.m16n8k32.row.col.s32.s8.s8.s32 "
        "{%0,%1,%2,%3}, {%4,%5,%6,%7}, {%8,%9}, {%0,%1,%2,%3};"
        : "+r"(c[0]), "+r"(c[1]), "+r"(c[2]), "+r"(c[3])
        : "r"(a[0]), "r"(a[1]), "r"(a[2]), "r"(a[3]), "r"(b0), "r"(b1));
}
__device__ __forceinline__ uint32_t pack_bf16(float x, float y) {
    __nv_bfloat162 t = __floats2bfloat162_rn(x, y);
    return *(uint32_t*)&t;
}

// ---------------- int8x3 GEMM on IMMA (mma.sync m16n8k32) ----------------------
// C[M,N] = dequant(A@B^T) + bias (opt ReLU). A,B two-level int8; B is [N,K].
// a = sA/127*(A1 + A2/254), b likewise. acc1 = A1B1, acc2 = A1B2 + A2B1.
// CTA 128x128, 512 thr (16 warps 4x4, warp 32x32). 4-stage cp.async, BK=32.
static constexpr uint32_t QTILE = 128 * 48;        // 6144 bytes per array
static constexpr uint32_t QSTAGE = 4 * QTILE;      // A1,A2,B1,B2 = 24576
static constexpr uint32_t QSMEM = 4 * QSTAGE;      // 98304

template <bool RELU>
__global__ __launch_bounds__(512, 1) void gemm_imma(
    const int8_t* __restrict__ A1, const int8_t* __restrict__ A2,
    const int8_t* __restrict__ B1, const int8_t* __restrict__ B2,
    const float* __restrict__ sA, const float* __restrict__ sB,
    const float* __restrict__ bias, float* __restrict__ C, int Nd, int Kd) {
    extern __shared__ char smem[];
    const uint32_t sb = smem_u32(smem);
    const int tid = threadIdx.x;
    const int wid = tid >> 5, lane = tid & 31;
    const int wm = wid & 3, wn = wid >> 2;
    const int bm = blockIdx.x * 128;
    const int bn = blockIdx.y * 128;
    const int NC = Kd >> 5;

    auto issue = [&](int c) {
        const int k0 = c << 5;
        const uint32_t base = sb + (c & 3) * QSTAGE;
#pragma unroll
        for (int it = 0; it < 2; it++) {
            int s = tid + it * 512;
            int arr = s >> 8, rem = s & 255, row = rem >> 1, half = rem & 1;
            const int8_t* src = (arr == 0) ? A1 : (arr == 1) ? A2 : (arr == 2) ? B1 : B2;
            int grow = ((arr < 2) ? bm : bn) + row;
            cp16(base + arr * QTILE + row * 48 + half * 16,
                 src + (size_t)grow * Kd + k0 + half * 16);
        }
    };

    issue(0); cp_commit();
    issue(1); cp_commit();
    issue(2); cp_commit();

    int acc1[2][4][4], acc2[2][4][4];
#pragma unroll
    for (int i = 0; i < 2; i++)
#pragma unroll
        for (int j = 0; j < 4; j++)
#pragma unroll
            for (int r = 0; r < 4; r++) { acc1[i][j][r] = 0; acc2[i][j][r] = 0; }

    // ldmatrix lane offsets
    const int a_row = (lane & 7) + ((lane >> 3) & 1) * 8;  // row within 16
    const int a_kh  = (lane >> 4) * 16;                    // k-half byte offset
    const int b_row = (lane & 7);
    const int b_kh  = ((lane >> 3) & 1) * 16;

    for (int c = 0; c < NC; c++) {
        cp_wait<2>();
        __syncthreads();
        if (c + 3 < NC) issue(c + 3);
        cp_commit();

        const uint32_t base = sb + (c & 3) * QSTAGE;
        uint32_t a1f[2][4], a2f[2][4], b1f[4][2], b2f[4][2];
#pragma unroll
        for (int mt = 0; mt < 2; mt++) {
            uint32_t ra = (uint32_t)(wm * 32 + mt * 16 + a_row) * 48 + a_kh;
            ldmat4(a1f[mt], base + ra);
            ldmat4(a2f[mt], base + QTILE + ra);
        }
#pragma unroll
        for (int ng = 0; ng < 4; ng++) {
            uint32_t rb = (uint32_t)(wn * 32 + ng * 8 + b_row) * 48 + b_kh;
            ldmat2(b1f[ng], base + 2 * QTILE + rb);
            ldmat2(b2f[ng], base + 3 * QTILE + rb);
        }
#pragma unroll
        for (int mt = 0; mt < 2; mt++)
#pragma unroll
            for (int ng = 0; ng < 4; ng++)
                imma16832(acc1[mt][ng], a1f[mt], b1f[ng][0], b1f[ng][1]);
#pragma unroll
        for (int mt = 0; mt < 2; mt++)
#pragma unroll
            for (int ng = 0; ng < 4; ng++) {
                imma16832(acc2[mt][ng], a1f[mt], b2f[ng][0], b2f[ng][1]);
                imma16832(acc2[mt][ng], a2f[mt], b1f[ng][0], b1f[ng][1]);
            }
    }

    const int g = lane >> 2, t = lane & 3;
    const float CNORM = 1.0f / 16129.0f;   // 1/(127*127)
    const float INV254 = 1.0f / 254.0f;
#pragma unroll
    for (int mt = 0; mt < 2; mt++) {
        int r0 = bm + wm * 32 + mt * 16 + g;
        float sa0 = sA[r0] * CNORM;
        float sa1 = sA[r0 + 8] * CNORM;
#pragma unroll
        for (int ng = 0; ng < 4; ng++) {
            int c0 = bn + wn * 32 + ng * 8 + t * 2;
            float sb0 = sB[c0], sb1 = sB[c0 + 1];
            float bx = bias[c0], by = bias[c0 + 1];
            float2 v0, v1;
            v0.x = sa0 * sb0 * ((float)acc1[mt][ng][0] + (float)acc2[mt][ng][0] * INV254) + bx;
            v0.y = sa0 * sb1 * ((float)acc1[mt][ng][1] + (float)acc2[mt][ng][1] * INV254) + by;
            v1.x = sa1 * sb0 * ((float)acc1[mt][ng][2] + (float)acc2[mt][ng][2] * INV254) + bx;
            v1.y = sa1 * sb1 * ((float)acc1[mt][ng][3] + (float)acc2[mt][ng][3] * INV254) + by;
            if (RELU) {
                v0.x = fmaxf(v0.x, 0.f); v0.y = fmaxf(v0.y, 0.f);
                v1.x = fmaxf(v1.x, 0.f); v1.y = fmaxf(v1.y, 0.f);
            }
            *(float2*)&C[(size_t)r0 * Nd + c0] = v0;
            *(float2*)&C[(size_t)(r0 + 8) * Nd + c0] = v1;
        }
    }
}

// ---------------- quantization kernels -----------------------------------------
__inline__ __device__ float block_reduce_max(float val) {
    __shared__ float sbuf[8];
    int lane = threadIdx.x & 31, wid = threadIdx.x >> 5;
#pragma unroll
    for (int o = 16; o; o >>= 1) val = fmaxf(val, __shfl_xor_sync(0xffffffffu, val, o));
    if (lane == 0) sbuf[wid] = val;
    __syncthreads();
    val = (threadIdx.x < 8) ? sbuf[threadIdx.x] : 0.f;
    if (wid == 0) {
#pragma unroll
        for (int o = 4; o; o >>= 1) val = fmaxf(val, __shfl_xor_sync(0xffffffffu, val, o));
        if (lane == 0) sbuf[0] = val;
    }
    __syncthreads();
    float r = sbuf[0];
    __syncthreads();
    return r;
}

// per-row two-level quant of activations: x[M][K] -> q1,q2 int8, s=absmax
__global__ void aquant_kernel(const float* __restrict__ x, int8_t* __restrict__ q1,
                              int8_t* __restrict__ q2, float* __restrict__ s, int K) {
    int row = blockIdx.x;
    const float* p = x + (size_t)row * K;
    const int nf = K >> 10;              // float4s per thread (256 thr * 4 elem)
    float4 v[4];
    float am = 0.f;
#pragma unroll
    for (int i = 0; i < 4; i++) {
        if (i < nf) {
            v[i] = ((const float4*)p)[threadIdx.x + i * 256];
            am = fmaxf(am, fmaxf(fmaxf(fabsf(v[i].x), fabsf(v[i].y)),
                                 fmaxf(fabsf(v[i].z), fabsf(v[i].w))));
        }
    }
    am = block_reduce_max(am);
    if (threadIdx.x == 0) s[row] = am;
    float inv = (am > 0.f) ? 127.0f / am : 0.f;
#pragma unroll
    for (int i = 0; i < 4; i++) {
        if (i < nf) {
            float vv[4] = {v[i].x, v[i].y, v[i].z, v[i].w};
            char4 c1, c2;
            signed char* p1 = (signed char*)&c1;
            signed char* p2 = (signed char*)&c2;
#pragma unroll
            for (int j = 0; j < 4; j++) {
                float tq = vv[j] * inv;
                float Q1 = rintf(tq);
                float Q2 = rintf((tq - Q1) * 254.0f);
                p1[j] = (signed char)Q1;
                p2[j] = (signed char)Q2;
            }
            size_t idx = (size_t)row * (K >> 2) + threadIdx.x + i * 256;
            ((char4*)q1)[idx] = c1;
            ((char4*)q2)[idx] = c2;
        }
    }
}

__global__ void zmax_kernel(float* __restrict__ s, int N) {
    int i = blockIdx.x * 256 + threadIdx.x;
    if (i < N) s[i] = 0.f;
}

// per-column absmax of W[K][N] into s[N]
__global__ void colmax_kernel(const float* __restrict__ W, float* __restrict__ s, int N) {
    int n = blockIdx.x * 256 + threadIdx.x;
    int k0 = blockIdx.y * 128;
    float m = 0.f;
#pragma unroll 4
    for (int k = 0; k < 128; k++)
        m = fmaxf(m, fabsf(W[(size_t)(k0 + k) * N + n]));
    atomicMax((int*)&s[n], __float_as_int(m));
}

// transpose + two-level quant: W[K][N] -> q1,q2 [N][K]
__global__ void tquant_kernel(const float* __restrict__ W, const float* __restrict__ smax,
                              int8_t* __restrict__ q1, int8_t* __restrict__ q2, int K, int N) {
    __shared__ float sblk[32][33];
    int n = blockIdx.x * 32 + threadIdx.x;
    int k = blockIdx.y * 32 + threadIdx.y;
    sblk[threadIdx.y][threadIdx.x] = W[(size_t)k * N + n];
    __syncthreads();
    int no = blockIdx.x * 32 + threadIdx.y;
    int ko = blockIdx.y * 32 + threadIdx.x;
    float am = smax[no];
    float inv = (am > 0.f) ? 127.0f / am : 0.f;
    float tq = sblk[threadIdx.x][threadIdx.y] * inv;
    float Q1 = rintf(tq);
    float Q2 = rintf((tq - Q1) * 254.0f);
    q1[(size_t)no * K + ko] = (int8_t)Q1;
    q2[(size_t)no * K + ko] = (int8_t)Q2;
}

// ---------------- embed + positional encoding ---------------------------------
__global__ void embed_kernel(const int* __restrict__ x, const float* __restrict__ emb,
                             float* __restrict__ h) {
    int row = blockIdx.x;
    int t = row & (cfg::T - 1);
    int tok = x[row];
    const float* e = emb + (size_t)tok * cfg::D;
    float* out = h + (size_t)row * cfg::D;
    int d0 = threadIdx.x * 4;
    float4 ev = *(const float4*)&e[d0];
    const float cfac = -0.017988946039015984f;
    int i0 = d0 >> 1;
    float f0 = expf((float)i0 * cfac);
    float f1 = expf((float)(i0 + 1) * cfac);
    float a0 = (float)t * f0, a1 = (float)t * f1;
    float4 o;
    o.x = ev.x + sinf(a0);
    o.y = ev.y + cosf(a0);
    o.z = ev.z + sinf(a1);
    o.w = ev.w + cosf(a1);
    *(float4*)&out[d0] = o;
}

// ---------------- HMMA flash attention (bf16x3, causal) -----------------------
static constexpr int FSTR = 72;

__global__ __launch_bounds__(128) void flash_hmma(
    const float* __restrict__ q, const float* __restrict__ k,
    const float* __restrict__ v, float* __restrict__ o) {
    __shared__ __nv_bfloat16 sQh[64 * FSTR], sQl[64 * FSTR];
    __shared__ __nv_bfloat16 sKh[64 * FSTR], sKl[64 * FSTR];
    __shared__ __nv_bfloat16 sVh[64 * FSTR], sVl[64 * FSTR];

    const int qi = gridDim.x - 1 - blockIdx.x;
    const int h = blockIdx.y, b = blockIdx.z;
    const int tid = threadIdx.x;
    const int wid = tid >> 5, lane = tid & 31;
    const size_t headoff = ((size_t)b * cfg::T) * cfg::D + (size_t)h * cfg::HD;

    const uint32_t uQh = smem_u32(sQh), uQl = smem_u32(sQl);
    const uint32_t uKh = smem_u32(sKh), uKl = smem_u32(sKl);
    const uint32_t uVh = smem_u32(sVh), uVl = smem_u32(sVl);

    const int a_r = lane & 15;
    const int a_c = (lane >> 4) << 3;
    const int b_r = (lane & 7) + ((lane >> 4) << 3);
    const int b_c = ((lane >> 3) & 1) << 3;
    const int g = lane >> 2, t = lane & 3;

#pragma unroll
    for (int it = 0; it < 8; it++) {
        int idx = tid + it * 128;
        int r = idx >> 4, dq = (idx & 15) * 4;
        float4 tv = *(const float4*)&q[headoff + (size_t)(qi * 64 + r) * cfg::D + dq];
        uint32_t h01 = pack_bf16(tv.x, tv.y);
        uint32_t h23 = pack_bf16(tv.z, tv.w);
        *(uint2*)&sQh[r * FSTR + dq] = make_uint2(h01, h23);
        __nv_bfloat162 hh0 = *(__nv_bfloat162*)&h01;
        __nv_bfloat162 hh1 = *(__nv_bfloat162*)&h23;
        uint32_t l01 = pack_bf16(tv.x - __bfloat162float(hh0.x), tv.y - __bfloat162float(hh0.y));
        uint32_t l23 = pack_bf16(tv.z - __bfloat162float(hh1.x), tv.w - __bfloat162float(hh1.y));
        *(uint2*)&sQl[r * FSTR + dq] = make_uint2(l01, l23);
    }

    float accO[8][4];
#pragma unroll
    for (int i = 0; i < 8; i++)
#pragma unroll
        for (int j = 0; j < 4; j++) accO[i][j] = 0.f;
    float m0 = -1e30f, m1 = -1e30f, l0 = 0.f, l1 = 0.f;

    for (int kt = 0; kt <= qi; kt++) {
        __syncthreads();
#pragma unroll
        for (int it = 0; it < 8; it++) {
            int idx = tid + it * 128;
            int r = idx >> 4, dq = (idx & 15) * 4;
            float4 tv = *(const float4*)&k[headoff + (size_t)(kt * 64 + r) * cfg::D + dq];
            uint32_t h01 = pack_bf16(tv.x, tv.y);
            uint32_t h23 = pack_bf16(tv.z, tv.w);
            *(uint2*)&sKh[r * FSTR + dq] = make_uint2(h01, h23);
            __nv_bfloat162 hh0 = *(__nv_bfloat162*)&h01;
            __nv_bfloat162 hh1 = *(__nv_bfloat162*)&h23;
            uint32_t l01 = pack_bf16(tv.x - __bfloat162float(hh0.x), tv.y - __bfloat162float(hh0.y));
            uint32_t l23 = pack_bf16(tv.z - __bfloat162float(hh1.x), tv.w - __bfloat162float(hh1.y));
            *(uint2*)&sKl[r * FSTR + dq] = make_uint2(l01, l23);

            float4 vv = *(const float4*)&v[headoff + (size_t)(kt * 64 + r) * cfg::D + dq];
            float vals[4] = {vv.x, vv.y, vv.z, vv.w};
#pragma unroll
            for (int j = 0; j < 4; j++) {
                __nv_bfloat16 hb = __float2bfloat16_rn(vals[j]);
                sVh[(dq + j) * FSTR + r] = hb;
                sVl[(dq + j) * FSTR + r] = __float2bfloat16_rn(vals[j] - __bfloat162float(hb));
            }
        }
        __syncthreads();

        float sa[8][4];
#pragma unroll
        for (int i = 0; i < 8; i++)
#pragma unroll
            for (int j = 0; j < 4; j++) sa[i][j] = 0.f;

        const uint32_t qsrc[3] = {uQh, uQh, uQl};
        const uint32_t ksrc[3] = {uKh, uKl, uKh};
#pragma unroll
        for (int cb = 0; cb < 3; cb++) {
#pragma unroll
            for (int kg = 0; kg < 4; kg++) {
                uint32_t af[4];
                ldmat4(af, qsrc[cb] + (uint32_t)(wid * 16 + a_r) * (FSTR * 2) + (kg * 16 + a_c) * 2);
#pragma unroll
                for (int gg = 0; gg < 4; gg++) {
                    uint32_t bf[4];
                    ldmat4(bf, ksrc[cb] + (uint32_t)(gg * 16 + b_r) * (FSTR * 2) + (kg * 16 + b_c) * 2);
                    mma16816(sa[gg * 2], af, bf[0], bf[1]);
                    mma16816(sa[gg * 2 + 1], af, bf[2], bf[3]);
                }
            }
        }

        const bool diag = (kt == qi);
#pragma unroll
        for (int nt = 0; nt < 8; nt++) {
            int c0 = nt * 8 + t * 2;
            sa[nt][0] *= 0.125f; sa[nt][1] *= 0.125f;
            sa[nt][2] *= 0.125f; sa[nt][3] *= 0.125f;
            if (diag) {
                int r0 = wid * 16 + g, r1 = r0 + 8;
                if (c0 > r0)     sa[nt][0] = -1e30f;
                if (c0 + 1 > r0) sa[nt][1] = -1e30f;
                if (c0 > r1)     sa[nt][2] = -1e30f;
                if (c0 + 1 > r1) sa[nt][3] = -1e30f;
            }
        }

        float mt0 = -1e30f, mt1 = -1e30f;
#pragma unroll
        for (int nt = 0; nt < 8; nt++) {
            mt0 = fmaxf(mt0, fmaxf(sa[nt][0], sa[nt][1]));
            mt1 = fmaxf(mt1, fmaxf(sa[nt][2], sa[nt][3]));
        }
#pragma unroll
        for (int off = 1; off <= 2; off <<= 1) {
            mt0 = fmaxf(mt0, __shfl_xor_sync(0xffffffffu, mt0, off));
            mt1 = fmaxf(mt1, __shfl_xor_sync(0xffffffffu, mt1, off));
        }
        float mn0 = fmaxf(m0, mt0), mn1 = fmaxf(m1, mt1);
        float al0 = __expf(m0 - mn0), al1 = __expf(m1 - mn1);
        m0 = mn0; m1 = mn1;

        float rs0 = 0.f, rs1 = 0.f;
#pragma unroll
        for (int nt = 0; nt < 8; nt++) {
            sa[nt][0] = __expf(sa[nt][0] - mn0);
            sa[nt][1] = __expf(sa[nt][1] - mn0);
            sa[nt][2] = __expf(sa[nt][2] - mn1);
            sa[nt][3] = __expf(sa[nt][3] - mn1);
            rs0 += sa[nt][0] + sa[nt][1];
            rs1 += sa[nt][2] + sa[nt][3];
        }
#pragma unroll
        for (int off = 1; off <= 2; off <<= 1) {
            rs0 += __shfl_xor_sync(0xffffffffu, rs0, off);
            rs1 += __shfl_xor_sync(0xffffffffu, rs1, off);
        }
        l0 = l0 * al0 + rs0;
        l1 = l1 * al1 + rs1;
#pragma unroll
        for (int nt = 0; nt < 8; nt++) {
            accO[nt][0] *= al0; accO[nt][1] *= al0;
            accO[nt][2] *= al1; accO[nt][3] *= al1;
        }

        uint32_t ph[4][4], pl[4][4];
#pragma unroll
        for (int kg = 0; kg < 4; kg++) {
            float p00 = sa[2 * kg][0],     p01 = sa[2 * kg][1];
            float p10 = sa[2 * kg][2],     p11 = sa[2 * kg][3];
            float p20 = sa[2 * kg + 1][0], p21 = sa[2 * kg + 1][1];
            float p30 = sa[2 * kg + 1][2], p31 = sa[2 * kg + 1][3];
            ph[kg][0] = pack_bf16(p00, p01);
            ph[kg][1] = pack_bf16(p10, p11);
            ph[kg][2] = pack_bf16(p20, p21);
            ph[kg][3] = pack_bf16(p30, p31);
            __nv_bfloat162 h0 = *(__nv_bfloat162*)&ph[kg][0];
            __nv_bfloat162 h1 = *(__nv_bfloat162*)&ph[kg][1];
            __nv_bfloat162 h2 = *(__nv_bfloat162*)&ph[kg][2];
            __nv_bfloat162 h3 = *(__nv_bfloat162*)&ph[kg][3];
            pl[kg][0] = pack_bf16(p00 - __bfloat162float(h0.x), p01 - __bfloat162float(h0.y));
            pl[kg][1] = pack_bf16(p10 - __bfloat162float(h1.x), p11 - __bfloat162float(h1.y));
            pl[kg][2] = pack_bf16(p20 - __bfloat162float(h2.x), p21 - __bfloat162float(h2.y));
            pl[kg][3] = pack_bf16(p30 - __bfloat162float(h3.x), p31 - __bfloat162float(h3.y));
        }

        const uint32_t vsrc[3] = {uVh, uVl, uVh};
#pragma unroll
        for (int cb = 0; cb < 3; cb++) {
            uint32_t (*pf)[4] = (cb == 2) ? pl : ph;
#pragma unroll
            for (int kg = 0; kg < 4; kg++) {
#pragma unroll
                for (int gg = 0; gg < 4; gg++) {
                    uint32_t bf[4];
                    ldmat4(bf, vsrc[cb] + (uint32_t)(gg * 16 + b_r) * (FSTR * 2) + (kg * 16 + b_c) * 2);
                    mma16816(accO[gg * 2], pf[kg], bf[0], bf[1]);
                    mma16816(accO[gg * 2 + 1], pf[kg], bf[2], bf[3]);
                }
            }
        }
    }

    float inv0 = 1.0f / l0, inv1 = 1.0f / l1;
    int row0 = qi * 64 + wid * 16 + g;
#pragma unroll
    for (int nt = 0; nt < 8; nt++) {
        int col = nt * 8 + t * 2;
        float2 v0 = make_float2(accO[nt][0] * inv0, accO[nt][1] * inv0);
        float2 v1 = make_float2(accO[nt][2] * inv1, accO[nt][3] * inv1);
        *(float2*)&o[headoff + (size_t)row0 * cfg::D + col] = v0;
        *(float2*)&o[headoff + (size_t)(row0 + 8) * cfg::D + col] = v1;
    }
}

// ---------------- layernorm (unbiased std) -------------------------------------
__inline__ __device__ float block_reduce_sum(float val) {
    __shared__ float sbuf[8];
    int lane = threadIdx.x & 31, wid = threadIdx.x >> 5;
#pragma unroll
    for (int o = 16; o; o >>= 1) val += __shfl_xor_sync(0xffffffffu, val, o);
    if (lane == 0) sbuf[wid] = val;
    __syncthreads();
    val = (threadIdx.x < 8) ? sbuf[threadIdx.x] : 0.f;
    if (wid == 0) {
#pragma unroll
        for (int o = 4; o; o >>= 1) val += __shfl_xor_sync(0xffffffffu, val, o);
        if (lane == 0) sbuf[0] = val;
    }
    __syncthreads();
    float r = sbuf[0];
    __syncthreads();
    return r;
}

__global__ void layernorm_kernel(float* __restrict__ h, const float* __restrict__ g,
                                 const float* __restrict__ be) {
    int row = blockIdx.x;
    float* p = h + (size_t)row * cfg::D;
    int d0 = threadIdx.x * 4;
    float4 xv = *(float4*)&p[d0];
    float s = xv.x + xv.y + xv.z + xv.w;
    s = block_reduce_sum(s);
    float mean = s * (1.0f / cfg::D);
    float dx[4] = {xv.x - mean, xv.y - mean, xv.z - mean, xv.w - mean};
    float sq = dx[0] * dx[0] + dx[1] * dx[1] + dx[2] * dx[2] + dx[3] * dx[3];
    sq = block_reduce_sum(sq);
    float stdv = sqrtf(sq / (float)(cfg::D - 1));
    float inv = 1.0f / (stdv + cfg::EPS);
    float4 gg = *(const float4*)&g[d0];
    float4 bb = *(const float4*)&be[d0];
    float4 o;
    o.x = dx[0] * inv * gg.x + bb.x;
    o.y = dx[1] * inv * gg.y + bb.y;
    o.z = dx[2] * inv * gg.z + bb.z;
    o.w = dx[3] * inv * gg.w + bb.w;
    *(float4*)&p[d0] = o;
}

// ---------------- row softmax over V=32000 -------------------------------------
__global__ void softmax_kernel(float* __restrict__ out) {
    int row = blockIdx.x;
    float* p = out + (size_t)row * cfg::V;
    float m = -1e30f, s = 0.f;
    for (int j = threadIdx.x; j < cfg::V; j += 256) {
        float xv = p[j];
        if (xv > m) { s = s * __expf(m - xv) + 1.0f; m = xv; }
        else        { s += __expf(xv - m); }
    }
    __shared__ float sm[256], ss[256];
    sm[threadIdx.x] = m; ss[threadIdx.x] = s;
    __syncthreads();
    for (int off = 128; off; off >>= 1) {
        if (threadIdx.x < off) {
            float m1 = sm[threadIdx.x], s1 = ss[threadIdx.x];
            float m2 = sm[threadIdx.x + off], s2 = ss[threadIdx.x + off];
            float mm = fmaxf(m1, m2);
            sm[threadIdx.x] = mm;
            ss[threadIdx.x] = s1 * __expf(m1 - mm) + s2 * __expf(m2 - mm);
        }
        __syncthreads();
    }
    float mall = sm[0];
    float inv = 1.0f / ss[0];
    for (int j = threadIdx.x; j < cfg::V; j += 256) {
        p[j] = __expf(p[j] - mall) * inv;
    }
}

// ---------------- host orchestration -------------------------------------------
extern "C" void kernel_launch(void* const* d_in, const int* in_sizes, int n_in,
                              void* d_out, int out_size) {
    using namespace cfg;
    const int*   x   = (const int*)d_in[0];
    const float* emb = (const float*)d_in[1];
    const float* Wq  = (const float*)d_in[2];
    const float* bq  = (const float*)d_in[3];
    const float* Wk  = (const float*)d_in[4];
    const float* bk  = (const float*)d_in[5];
    const float* Wv  = (const float*)d_in[6];
    const float* bv  = (const float*)d_in[7];
    const float* Wo  = (const float*)d_in[8];
    const float* bo  = (const float*)d_in[9];
    const float* g1  = (const float*)d_in[10];
    const float* be1 = (const float*)d_in[11];
    const float* W1  = (const float*)d_in[12];
    const float* bf1 = (const float*)d_in[13];
    const float* W2  = (const float*)d_in[14];
    const float* bf2 = (const float*)d_in[15];
    const float* g2  = (const float*)d_in[16];
    const float* be2 = (const float*)d_in[17];
    const float* Wl  = (const float*)d_in[18];
    const float* bl  = (const float*)d_in[19];
    float* out = (float*)d_out;

    float *h, *q, *k, *v, *o, *f, *as, *ws;
    int8_t *a1, *a2, *w1q, *w2q;
    cudaGetSymbolAddress((void**)&h, g_h);
    cudaGetSymbolAddress((void**)&q, g_q);
    cudaGetSymbolAddress((void**)&k, g_k);
    cudaGetSymbolAddress((void**)&v, g_v);
    cudaGetSymbolAddress((void**)&o, g_o);
    cudaGetSymbolAddress((void**)&f, g_f);
    cudaGetSymbolAddress((void**)&a1, g_a1);
    cudaGetSymbolAddress((void**)&a2, g_a2);
    cudaGetSymbolAddress((void**)&as, g_as);
    cudaGetSymbolAddress((void**)&w1q, g_wq1);
    cudaGetSymbolAddress((void**)&w2q, g_wq2);
    cudaGetSymbolAddress((void**)&ws, g_ws);

    cudaFuncSetAttribute(gemm_imma<false>, cudaFuncAttributeMaxDynamicSharedMemorySize, QSMEM);
    cudaFuncSetAttribute(gemm_imma<true>,  cudaFuncAttributeMaxDynamicSharedMemorySize, QSMEM);

    dim3 tb(32, 32);

    // --- Wq prep + embed + act quant + Q gemm (gemm at launch index 5 for ncu) ---
    zmax_kernel<<<D / 256, 256>>>(ws, D);                                  // 0
    colmax_kernel<<<dim3(D / 256, D / 128), 256>>>(Wq, ws, D);             // 1
    tquant_kernel<<<dim3(D / 32, D / 32), tb>>>(Wq, ws, w1q, w2q, D, D);   // 2
    embed_kernel<<<M, 256>>>(x, emb, h);                                   // 3
    aquant_kernel<<<M, 256>>>(h, a1, a2, as, D);                           // 4
    gemm_imma<false><<<dim3(M / 128, D / 128), 512, QSMEM>>>(              // 5
        a1, a2, w1q, w2q, as, ws, bq, q, D, D);

    zmax_kernel<<<D / 256, 256>>>(ws, D);
    colmax_kernel<<<dim3(D / 256, D / 128), 256>>>(Wk, ws, D);
    tquant_kernel<<<dim3(D / 32, D / 32), tb>>>(Wk, ws, w1q, w2q, D, D);
    gemm_imma<false><<<dim3(M / 128, D / 128), 512, QSMEM>>>(a1, a2, w1q, w2q, as, ws, bk, k, D, D);

    zmax_kernel<<<D / 256, 256>>>(ws, D);
    colmax_kernel<<<dim3(D / 256, D / 128), 256>>>(Wv, ws, D);
    tquant_kernel<<<dim3(D / 32, D / 32), tb>>>(Wv, ws, w1q, w2q, D, D);
    gemm_imma<false><<<dim3(M / 128, D / 128), 512, QSMEM>>>(a1, a2, w1q, w2q, as, ws, bv, v, D, D);

    flash_hmma<<<dim3(T / 64, H, B), 128>>>(q, k, v, o);

    zmax_kernel<<<D / 256, 256>>>(ws, D);
    colmax_kernel<<<dim3(D / 256, D / 128), 256>>>(Wo, ws, D);
    tquant_kernel<<<dim3(D / 32, D / 32), tb>>>(Wo, ws, w1q, w2q, D, D);
    aquant_kernel<<<M, 256>>>(o, a1, a2, as, D);
    gemm_imma<false><<<dim3(M / 128, D / 128), 512, QSMEM>>>(a1, a2, w1q, w2q, as, ws, bo, h, D, D);
    layernorm_kernel<<<M, 256>>>(h, g1, be1);

    zmax_kernel<<<F / 256, 256>>>(ws, F);
    colmax_kernel<<<dim3(F / 256, D / 128), 256>>>(W1, ws, F);
    tquant_kernel<<<dim3(F / 32, D / 32), tb>>>(W1, ws, w1q, w2q, D, F);
    aquant_kernel<<<M, 256>>>(h, a1, a2, as, D);
    gemm_imma<true><<<dim3(M / 128, F / 128), 512, QSMEM>>>(a1, a2, w1q, w2q, as, ws, bf1, f, F, D);

    zmax_kernel<<<D / 256, 256>>>(ws, D);
    colmax_kernel<<<dim3(D / 256, F / 128), 256>>>(W2, ws, D);
    tquant_kernel<<<dim3(D / 32, F / 32), tb>>>(W2, ws, w1q, w2q, F, D);
    aquant_kernel<<<M, 256>>>(f, a1, a2, as, F);
    gemm_imma<false><<<dim3(M / 128, D / 128), 512, QSMEM>>>(a1, a2, w1q, w2q, as, ws, bf2, o, D, F);
    layernorm_kernel<<<M, 256>>>(o, g2, be2);

    zmax_kernel<<<V / 256, 256>>>(ws, V);
    colmax_kernel<<<dim3(V / 256, D / 128), 256>>>(Wl, ws, V);
    tquant_kernel<<<dim3(V / 32, D / 32), tb>>>(Wl, ws, w1q, w2q, D, V);
    aquant_kernel<<<M, 256>>>(o, a1, a2, as, D);
    gemm_imma<false><<<dim3(M / 128, V / 128), 512, QSMEM>>>(a1, a2, w1q, w2q, as, ws, bl, out, V, D);

    softmax_kernel<<<M, 256>>>(out);
}

// round 6
// speedup vs baseline: 3.1329x; 3.1329x over previous
#include <cuda_runtime.h>
#include <cuda_bf16.h>
#include <cuda_fp16.h>
#include <math.h>
#include <stdint.h>

// ---------------- problem constants ----------------
namespace cfg {
constexpr int B = 2, T = 2048, D = 1024, H = 16, HD = 64, F = 4096, V = 32000;
constexpr int M = B * T;
constexpr float EPS = 1e-6f;
}

// ---------------- scratch ----------------------------------------------------
__device__ float g_h[cfg::M * cfg::D];
__device__ float g_q[cfg::M * cfg::D];
__device__ float g_k[cfg::M * cfg::D];
__device__ float g_v[cfg::M * cfg::D];
__device__ float g_o[cfg::M * cfg::D];
__device__ float g_f[(size_t)cfg::M * cfg::F];

__device__ __nv_bfloat16 g_ah[(size_t)cfg::M * cfg::F];
__device__ __nv_bfloat16 g_al[(size_t)cfg::M * cfg::F];
__device__ __nv_bfloat16 g_wqh[cfg::D * cfg::D], g_wql[cfg::D * cfg::D];
__device__ __nv_bfloat16 g_wkh[cfg::D * cfg::D], g_wkl[cfg::D * cfg::D];
__device__ __nv_bfloat16 g_wvh[cfg::D * cfg::D], g_wvl[cfg::D * cfg::D];
__device__ __nv_bfloat16 g_woh[cfg::D * cfg::D], g_wol[cfg::D * cfg::D];
__device__ __nv_bfloat16 g_w1h[(size_t)cfg::D * cfg::F], g_w1l[(size_t)cfg::D * cfg::F];
__device__ __nv_bfloat16 g_w2h[(size_t)cfg::D * cfg::F], g_w2l[(size_t)cfg::D * cfg::F];
__device__ __nv_bfloat16 g_wlh[(size_t)cfg::V * cfg::D];   // holds fp16 for logits

// ---------------- PTX helpers -------------------------------------------------
__device__ __forceinline__ uint32_t smem_u32(const void* p) {
    uint32_t a;
    asm("{ .reg .u64 t; cvta.to.shared.u64 t, %1; cvt.u32.u64 %0, t; }" : "=r"(a) : "l"(p));
    return a;
}
__device__ __forceinline__ void cp16(uint32_t dst, const void* src) {
    asm volatile("cp.async.cg.shared.global [%0], [%1], 16;" :: "r"(dst), "l"(src));
}
__device__ __forceinline__ void cp_commit() {
    asm volatile("cp.async.commit_group;" ::: "memory");
}
template <int N>
__device__ __forceinline__ void cp_wait() {
    asm volatile("cp.async.wait_group %0;" :: "n"(N) : "memory");
}
__device__ __forceinline__ void ldmat4(uint32_t* r, uint32_t addr) {
    asm volatile("ldmatrix.sync.aligned.m8n8.x4.shared.b16 {%0,%1,%2,%3}, [%4];"
                 : "=r"(r[0]), "=r"(r[1]), "=r"(r[2]), "=r"(r[3]) : "r"(addr));
}
__device__ __forceinline__ void mma16816(float* c, const uint32_t* a, uint32_t b0, uint32_t b1) {
    asm volatile(
        "mma.sync.aligned.m16n8k16.row.col.f32.bf16.bf16.f32 "
        "{%0,%1,%2,%3}, {%4,%5,%6,%7}, {%8,%9}, {%0,%1,%2,%3};"
        : "+f"(c[0]), "+f"(c[1]), "+f"(c[2]), "+f"(c[3])
        : "r"(a[0]), "r"(a[1]), "r"(a[2]), "r"(a[3]), "r"(b0), "r"(b1));
}
__device__ __forceinline__ void mma16816h(float* c, const uint32_t* a, uint32_t b0, uint32_t b1) {
    asm volatile(
        "mma.sync.aligned.m16n8k16.row.col.f32.f16.f16.f32 "
        "{%0,%1,%2,%3}, {%4,%5,%6,%7}, {%8,%9}, {%0,%1,%2,%3};"
        : "+f"(c[0]), "+f"(c[1]), "+f"(c[2]), "+f"(c[3])
        : "r"(a[0]), "r"(a[1]), "r"(a[2]), "r"(a[3]), "r"(b0), "r"(b1));
}
__device__ __forceinline__ uint32_t pack_bf16(float x, float y) {
    __nv_bfloat162 t = __floats2bfloat162_rn(x, y);
    return *(uint32_t*)&t;
}

// ---------------- fused bf16x3 GEMM on HMMA (R4-proven) ------------------------
static constexpr uint32_t GA_BYTES = 128 * 48;
static constexpr uint32_t GB_BYTES = 256 * 48;
static constexpr uint32_t GSTAGE = 2 * GA_BYTES + 2 * GB_BYTES;
static constexpr uint32_t GEMM_SMEM = 4 * GSTAGE;

template <bool RELU>
__global__ __launch_bounds__(512, 1) void gemm_hmma(
    const __nv_bfloat16* __restrict__ Ah, const __nv_bfloat16* __restrict__ Al,
    const __nv_bfloat16* __restrict__ Bh, const __nv_bfloat16* __restrict__ Bl,
    const float* __restrict__ bias, float* __restrict__ C, int Nd, int Kd) {
    extern __shared__ char smem[];
    const uint32_t sb = smem_u32(smem);
    const int tid = threadIdx.x;
    const int wid = tid >> 5, lane = tid & 31;
    const int wm = wid & 1, wn = wid >> 1;
    const int bm = blockIdx.x * 128;
    const int bn = blockIdx.y * 256;
    const int NC = Kd >> 4;

    const int r2 = tid >> 1, s2 = tid & 1;

    auto issue_chunk = [&](int c) {
        const int lk = c << 4;
        uint32_t base = sb + (c & 3) * GSTAGE;
        if (tid < 256) {
            cp16(base + r2 * 48 + s2 * 16, Ah + (size_t)(bm + r2) * Kd + lk + s2 * 8);
        } else {
            int rr = (tid - 256) >> 1, ss = (tid - 256) & 1;
            cp16(base + GA_BYTES + rr * 48 + ss * 16,
                 Al + (size_t)(bm + rr) * Kd + lk + ss * 8);
        }
        cp16(base + 2 * GA_BYTES + r2 * 48 + s2 * 16,
             Bh + (size_t)(bn + r2) * Kd + lk + s2 * 8);
        cp16(base + 2 * GA_BYTES + GB_BYTES + r2 * 48 + s2 * 16,
             Bl + (size_t)(bn + r2) * Kd + lk + s2 * 8);
    };

    issue_chunk(0); cp_commit();
    issue_chunk(1); cp_commit();
    issue_chunk(2); cp_commit();

    float acc[4][4][4];
#pragma unroll
    for (int i = 0; i < 4; i++)
#pragma unroll
        for (int j = 0; j < 4; j++)
#pragma unroll
            for (int r = 0; r < 4; r++) acc[i][j][r] = 0.f;

    const int a_r = lane & 15;
    const int a_c = (lane >> 4) << 3;
    const int b_r = (lane & 7) + ((lane >> 4) << 3);
    const int b_c = ((lane >> 3) & 1) << 3;

    for (int c = 0; c < NC; c++) {
        cp_wait<2>();
        __syncthreads();
        if (c + 3 < NC) issue_chunk(c + 3);
        cp_commit();

        const uint32_t base = sb + (c & 3) * GSTAGE;
        const uint32_t sAh = base, sAl = base + GA_BYTES;
        const uint32_t sBh = base + 2 * GA_BYTES, sBl = sBh + GB_BYTES;

        uint32_t aH[4][4], aL[4][4], bH[2][4], bL[2][4];
#pragma unroll
        for (int mt = 0; mt < 4; mt++)
            ldmat4(aH[mt], sAh + (uint32_t)(wm * 64 + mt * 16 + a_r) * 48 + a_c * 2);
#pragma unroll
        for (int g = 0; g < 2; g++)
            ldmat4(bH[g], sBh + (uint32_t)(wn * 32 + g * 16 + b_r) * 48 + b_c * 2);
#pragma unroll
        for (int mt = 0; mt < 4; mt++)
#pragma unroll
            for (int nt = 0; nt < 4; nt++)
                mma16816(acc[mt][nt], aH[mt], bH[nt >> 1][(nt & 1) * 2], bH[nt >> 1][(nt & 1) * 2 + 1]);
#pragma unroll
        for (int mt = 0; mt < 4; mt++)
            ldmat4(aL[mt], sAl + (uint32_t)(wm * 64 + mt * 16 + a_r) * 48 + a_c * 2);
#pragma unroll
        for (int mt = 0; mt < 4; mt++)
#pragma unroll
            for (int nt = 0; nt < 4; nt++)
                mma16816(acc[mt][nt], aL[mt], bH[nt >> 1][(nt & 1) * 2], bH[nt >> 1][(nt & 1) * 2 + 1]);
#pragma unroll
        for (int g = 0; g < 2; g++)
            ldmat4(bL[g], sBl + (uint32_t)(wn * 32 + g * 16 + b_r) * 48 + b_c * 2);
#pragma unroll
        for (int mt = 0; mt < 4; mt++)
#pragma unroll
            for (int nt = 0; nt < 4; nt++)
                mma16816(acc[mt][nt], aH[mt], bL[nt >> 1][(nt & 1) * 2], bL[nt >> 1][(nt & 1) * 2 + 1]);
    }

    const int g = lane >> 2, t = lane & 3;
#pragma unroll
    for (int mt = 0; mt < 4; mt++) {
#pragma unroll
        for (int nt = 0; nt < 4; nt++) {
            int row0 = bm + wm * 64 + mt * 16 + g;
            int col = bn + wn * 32 + nt * 8 + t * 2;
            float bx = bias[col], by = bias[col + 1];
            float2 v0, v1;
            v0.x = acc[mt][nt][0] + bx; v0.y = acc[mt][nt][1] + by;
            v1.x = acc[mt][nt][2] + bx; v1.y = acc[mt][nt][3] + by;
            if (RELU) {
                v0.x = fmaxf(v0.x, 0.f); v0.y = fmaxf(v0.y, 0.f);
                v1.x = fmaxf(v1.x, 0.f); v1.y = fmaxf(v1.y, 0.f);
            }
            *(float2*)&C[(size_t)row0 * Nd + col] = v0;
            *(float2*)&C[(size_t)(row0 + 8) * Nd + col] = v1;
        }
    }
}

// ---------------- fp16 single-product GEMM (logits) ----------------------------
// C[M,N] = A@B^T + bias. A [M,K] fp16, B [N,K] fp16. CTA 128x256, BK=32,
// 512 thr (16 warps 2x8), 4-stage cp.async, 80B stride.
static constexpr uint32_t HA_BYTES = 128 * 80;             // 10240
static constexpr uint32_t HB_BYTES = 256 * 80;             // 20480
static constexpr uint32_t HSTAGE = HA_BYTES + HB_BYTES;    // 30720
static constexpr uint32_t HALF_SMEM = 4 * HSTAGE;          // 122880

__global__ __launch_bounds__(512, 1) void gemm_half(
    const __half* __restrict__ A, const __half* __restrict__ B,
    const float* __restrict__ bias, float* __restrict__ C, int Nd, int Kd) {
    extern __shared__ char smem[];
    const uint32_t sb = smem_u32(smem);
    const int tid = threadIdx.x;
    const int wid = tid >> 5, lane = tid & 31;
    const int wm = wid & 1, wn = wid >> 1;
    const int bm = blockIdx.x * 128;
    const int bn = blockIdx.y * 256;
    const int NC = Kd >> 5;

    const int arow = tid >> 2, aseg = tid & 3;

    auto issue = [&](int c) {
        const int k0 = c << 5;
        const uint32_t base = sb + (c & 3) * HSTAGE;
        cp16(base + arow * 80 + aseg * 16, A + (size_t)(bm + arow) * Kd + k0 + aseg * 8);
#pragma unroll
        for (int it = 0; it < 2; it++) {
            int i = tid + it * 512;
            int br = i >> 2, bs = i & 3;
            cp16(base + HA_BYTES + br * 80 + bs * 16,
                 B + (size_t)(bn + br) * Kd + k0 + bs * 8);
        }
    };

    issue(0); cp_commit();
    issue(1); cp_commit();
    issue(2); cp_commit();

    float acc[4][4][4];
#pragma unroll
    for (int i = 0; i < 4; i++)
#pragma unroll
        for (int j = 0; j < 4; j++)
#pragma unroll
            for (int r = 0; r < 4; r++) acc[i][j][r] = 0.f;

    const int a_r = lane & 15;
    const int a_c = (lane >> 4) << 3;
    const int b_r = (lane & 7) + ((lane >> 4) << 3);
    const int b_c = ((lane >> 3) & 1) << 3;

    for (int c = 0; c < NC; c++) {
        cp_wait<2>();
        __syncthreads();
        if (c + 3 < NC) issue(c + 3);
        cp_commit();

        const uint32_t sA = sb + (c & 3) * HSTAGE;
        const uint32_t sB = sA + HA_BYTES;
#pragma unroll
        for (int kk = 0; kk < 2; kk++) {
            uint32_t a[4][4], b[2][4];
#pragma unroll
            for (int mt = 0; mt < 4; mt++)
                ldmat4(a[mt], sA + (uint32_t)(wm * 64 + mt * 16 + a_r) * 80
                              + (uint32_t)(kk * 16 + a_c) * 2);
#pragma unroll
            for (int g = 0; g < 2; g++)
                ldmat4(b[g], sB + (uint32_t)(wn * 32 + g * 16 + b_r) * 80
                             + (uint32_t)(kk * 16 + b_c) * 2);
#pragma unroll
            for (int mt = 0; mt < 4; mt++)
#pragma unroll
                for (int nt = 0; nt < 4; nt++)
                    mma16816h(acc[mt][nt], a[mt],
                              b[nt >> 1][(nt & 1) * 2], b[nt >> 1][(nt & 1) * 2 + 1]);
        }
    }

    const int g = lane >> 2, t = lane & 3;
#pragma unroll
    for (int mt = 0; mt < 4; mt++) {
#pragma unroll
        for (int nt = 0; nt < 4; nt++) {
            int row0 = bm + wm * 64 + mt * 16 + g;
            int col = bn + wn * 32 + nt * 8 + t * 2;
            float2 v0, v1;
            v0.x = acc[mt][nt][0] + bias[col];
            v0.y = acc[mt][nt][1] + bias[col + 1];
            v1.x = acc[mt][nt][2] + bias[col];
            v1.y = acc[mt][nt][3] + bias[col + 1];
            *(float2*)&C[(size_t)row0 * Nd + col] = v0;
            *(float2*)&C[(size_t)(row0 + 8) * Nd + col] = v1;
        }
    }
}

// ---------------- split fp32 -> bf16 hi/lo ------------------------------------
__global__ void split_kernel(const float* __restrict__ x, __nv_bfloat16* __restrict__ hi,
                             __nv_bfloat16* __restrict__ lo, int n4) {
    int i = blockIdx.x * blockDim.x + threadIdx.x;
    if (i >= n4) return;
    float4 v = ((const float4*)x)[i];
    __nv_bfloat16 h0 = __float2bfloat16_rn(v.x);
    __nv_bfloat16 h1 = __float2bfloat16_rn(v.y);
    __nv_bfloat16 h2 = __float2bfloat16_rn(v.z);
    __nv_bfloat16 h3 = __float2bfloat16_rn(v.w);
    ((__nv_bfloat162*)hi)[i * 2 + 0] = __halves2bfloat162(h0, h1);
    ((__nv_bfloat162*)hi)[i * 2 + 1] = __halves2bfloat162(h2, h3);
    __nv_bfloat16 l0 = __float2bfloat16_rn(v.x - __bfloat162float(h0));
    __nv_bfloat16 l1 = __float2bfloat16_rn(v.y - __bfloat162float(h1));
    __nv_bfloat16 l2 = __float2bfloat16_rn(v.z - __bfloat162float(h2));
    __nv_bfloat16 l3 = __float2bfloat16_rn(v.w - __bfloat162float(h3));
    ((__nv_bfloat162*)lo)[i * 2 + 0] = __halves2bfloat162(l0, l1);
    ((__nv_bfloat162*)lo)[i * 2 + 1] = __halves2bfloat162(l2, l3);
}

// ---------------- fp32 -> fp16 convert ------------------------------------------
__global__ void tohalf_kernel(const float* __restrict__ x, __half* __restrict__ y, int n4) {
    int i = blockIdx.x * blockDim.x + threadIdx.x;
    if (i >= n4) return;
    float4 v = ((const float4*)x)[i];
    ((__half2*)y)[i * 2 + 0] = __floats2half2_rn(v.x, v.y);
    ((__half2*)y)[i * 2 + 1] = __floats2half2_rn(v.z, v.w);
}

// ---------------- transpose + split weight: W[K,N] -> hi/lo [N,K] --------------
__global__ void tsplit_kernel(const float* __restrict__ W, __nv_bfloat16* __restrict__ hi,
                              __nv_bfloat16* __restrict__ lo, int K, int N) {
    __shared__ float s[32][33];
    int n = blockIdx.x * 32 + threadIdx.x;
    int k = blockIdx.y * 32 + threadIdx.y;
    s[threadIdx.y][threadIdx.x] = W[(size_t)k * N + n];
    __syncthreads();
    int no = blockIdx.x * 32 + threadIdx.y;
    int ko = blockIdx.y * 32 + threadIdx.x;
    float v = s[threadIdx.x][threadIdx.y];
    __nv_bfloat16 h = __float2bfloat16_rn(v);
    hi[(size_t)no * K + ko] = h;
    lo[(size_t)no * K + ko] = __float2bfloat16_rn(v - __bfloat162float(h));
}

// transpose to fp16: W[K,N] -> [N,K] half
__global__ void thalf_kernel(const float* __restrict__ W, __half* __restrict__ out,
                             int K, int N) {
    __shared__ float s[32][33];
    int n = blockIdx.x * 32 + threadIdx.x;
    int k = blockIdx.y * 32 + threadIdx.y;
    s[threadIdx.y][threadIdx.x] = W[(size_t)k * N + n];
    __syncthreads();
    int no = blockIdx.x * 32 + threadIdx.y;
    int ko = blockIdx.y * 32 + threadIdx.x;
    out[(size_t)no * K + ko] = __float2half_rn(s[threadIdx.x][threadIdx.y]);
}

// ---------------- embed + positional encoding ---------------------------------
__global__ void embed_kernel(const int* __restrict__ x, const float* __restrict__ emb,
                             float* __restrict__ h) {
    int row = blockIdx.x;
    int t = row & (cfg::T - 1);
    int tok = x[row];
    const float* e = emb + (size_t)tok * cfg::D;
    float* out = h + (size_t)row * cfg::D;
    int d0 = threadIdx.x * 4;
    float4 ev = *(const float4*)&e[d0];
    const float cfac = -0.017988946039015984f;
    int i0 = d0 >> 1;
    float f0 = expf((float)i0 * cfac);
    float f1 = expf((float)(i0 + 1) * cfac);
    float a0 = (float)t * f0, a1 = (float)t * f1;
    float4 o;
    o.x = ev.x + sinf(a0);
    o.y = ev.y + cosf(a0);
    o.z = ev.z + sinf(a1);
    o.w = ev.w + cosf(a1);
    *(float4*)&out[d0] = o;
}

// ---------------- HMMA flash attention (bf16x3, causal) -----------------------
static constexpr int FSTR = 72;

__global__ __launch_bounds__(128) void flash_hmma(
    const float* __restrict__ q, const float* __restrict__ k,
    const float* __restrict__ v, float* __restrict__ o) {
    __shared__ __nv_bfloat16 sQh[64 * FSTR], sQl[64 * FSTR];
    __shared__ __nv_bfloat16 sKh[64 * FSTR], sKl[64 * FSTR];
    __shared__ __nv_bfloat16 sVh[64 * FSTR], sVl[64 * FSTR];

    const int qi = gridDim.x - 1 - blockIdx.x;
    const int h = blockIdx.y, b = blockIdx.z;
    const int tid = threadIdx.x;
    const int wid = tid >> 5, lane = tid & 31;
    const size_t headoff = ((size_t)b * cfg::T) * cfg::D + (size_t)h * cfg::HD;

    const uint32_t uQh = smem_u32(sQh), uQl = smem_u32(sQl);
    const uint32_t uKh = smem_u32(sKh), uKl = smem_u32(sKl);
    const uint32_t uVh = smem_u32(sVh), uVl = smem_u32(sVl);

    const int a_r = lane & 15;
    const int a_c = (lane >> 4) << 3;
    const int b_r = (lane & 7) + ((lane >> 4) << 3);
    const int b_c = ((lane >> 3) & 1) << 3;
    const int g = lane >> 2, t = lane & 3;

#pragma unroll
    for (int it = 0; it < 8; it++) {
        int idx = tid + it * 128;
        int r = idx >> 4, dq = (idx & 15) * 4;
        float4 tv = *(const float4*)&q[headoff + (size_t)(qi * 64 + r) * cfg::D + dq];
        uint32_t h01 = pack_bf16(tv.x, tv.y);
        uint32_t h23 = pack_bf16(tv.z, tv.w);
        *(uint2*)&sQh[r * FSTR + dq] = make_uint2(h01, h23);
        __nv_bfloat162 hh0 = *(__nv_bfloat162*)&h01;
        __nv_bfloat162 hh1 = *(__nv_bfloat162*)&h23;
        uint32_t l01 = pack_bf16(tv.x - __bfloat162float(hh0.x), tv.y - __bfloat162float(hh0.y));
        uint32_t l23 = pack_bf16(tv.z - __bfloat162float(hh1.x), tv.w - __bfloat162float(hh1.y));
        *(uint2*)&sQl[r * FSTR + dq] = make_uint2(l01, l23);
    }

    float accO[8][4];
#pragma unroll
    for (int i = 0; i < 8; i++)
#pragma unroll
        for (int j = 0; j < 4; j++) accO[i][j] = 0.f;
    float m0 = -1e30f, m1 = -1e30f, l0 = 0.f, l1 = 0.f;

    for (int kt = 0; kt <= qi; kt++) {
        __syncthreads();
#pragma unroll
        for (int it = 0; it < 8; it++) {
            int idx = tid + it * 128;
            int r = idx >> 4, dq = (idx & 15) * 4;
            float4 tv = *(const float4*)&k[headoff + (size_t)(kt * 64 + r) * cfg::D + dq];
            uint32_t h01 = pack_bf16(tv.x, tv.y);
            uint32_t h23 = pack_bf16(tv.z, tv.w);
            *(uint2*)&sKh[r * FSTR + dq] = make_uint2(h01, h23);
            __nv_bfloat162 hh0 = *(__nv_bfloat162*)&h01;
            __nv_bfloat162 hh1 = *(__nv_bfloat162*)&h23;
            uint32_t l01 = pack_bf16(tv.x - __bfloat162float(hh0.x), tv.y - __bfloat162float(hh0.y));
            uint32_t l23 = pack_bf16(tv.z - __bfloat162float(hh1.x), tv.w - __bfloat162float(hh1.y));
            *(uint2*)&sKl[r * FSTR + dq] = make_uint2(l01, l23);

            float4 vv = *(const float4*)&v[headoff + (size_t)(kt * 64 + r) * cfg::D + dq];
            float vals[4] = {vv.x, vv.y, vv.z, vv.w};
#pragma unroll
            for (int j = 0; j < 4; j++) {
                __nv_bfloat16 hb = __float2bfloat16_rn(vals[j]);
                sVh[(dq + j) * FSTR + r] = hb;
                sVl[(dq + j) * FSTR + r] = __float2bfloat16_rn(vals[j] - __bfloat162float(hb));
            }
        }
        __syncthreads();

        float sa[8][4];
#pragma unroll
        for (int i = 0; i < 8; i++)
#pragma unroll
            for (int j = 0; j < 4; j++) sa[i][j] = 0.f;

        const uint32_t qsrc[3] = {uQh, uQh, uQl};
        const uint32_t ksrc[3] = {uKh, uKl, uKh};
#pragma unroll
        for (int cb = 0; cb < 3; cb++) {
#pragma unroll
            for (int kg = 0; kg < 4; kg++) {
                uint32_t af[4];
                ldmat4(af, qsrc[cb] + (uint32_t)(wid * 16 + a_r) * (FSTR * 2) + (kg * 16 + a_c) * 2);
#pragma unroll
                for (int gg = 0; gg < 4; gg++) {
                    uint32_t bf[4];
                    ldmat4(bf, ksrc[cb] + (uint32_t)(gg * 16 + b_r) * (FSTR * 2) + (kg * 16 + b_c) * 2);
                    mma16816(sa[gg * 2], af, bf[0], bf[1]);
                    mma16816(sa[gg * 2 + 1], af, bf[2], bf[3]);
                }
            }
        }

        const bool diag = (kt == qi);
#pragma unroll
        for (int nt = 0; nt < 8; nt++) {
            int c0 = nt * 8 + t * 2;
            sa[nt][0] *= 0.125f; sa[nt][1] *= 0.125f;
            sa[nt][2] *= 0.125f; sa[nt][3] *= 0.125f;
            if (diag) {
                int r0 = wid * 16 + g, r1 = r0 + 8;
                if (c0 > r0)     sa[nt][0] = -1e30f;
                if (c0 + 1 > r0) sa[nt][1] = -1e30f;
                if (c0 > r1)     sa[nt][2] = -1e30f;
                if (c0 + 1 > r1) sa[nt][3] = -1e30f;
            }
        }

        float mt0 = -1e30f, mt1 = -1e30f;
#pragma unroll
        for (int nt = 0; nt < 8; nt++) {
            mt0 = fmaxf(mt0, fmaxf(sa[nt][0], sa[nt][1]));
            mt1 = fmaxf(mt1, fmaxf(sa[nt][2], sa[nt][3]));
        }
#pragma unroll
        for (int off = 1; off <= 2; off <<= 1) {
            mt0 = fmaxf(mt0, __shfl_xor_sync(0xffffffffu, mt0, off));
            mt1 = fmaxf(mt1, __shfl_xor_sync(0xffffffffu, mt1, off));
        }
        float mn0 = fmaxf(m0, mt0), mn1 = fmaxf(m1, mt1);
        float al0 = __expf(m0 - mn0), al1 = __expf(m1 - mn1);
        m0 = mn0; m1 = mn1;

        float rs0 = 0.f, rs1 = 0.f;
#pragma unroll
        for (int nt = 0; nt < 8; nt++) {
            sa[nt][0] = __expf(sa[nt][0] - mn0);
            sa[nt][1] = __expf(sa[nt][1] - mn0);
            sa[nt][2] = __expf(sa[nt][2] - mn1);
            sa[nt][3] = __expf(sa[nt][3] - mn1);
            rs0 += sa[nt][0] + sa[nt][1];
            rs1 += sa[nt][2] + sa[nt][3];
        }
#pragma unroll
        for (int off = 1; off <= 2; off <<= 1) {
            rs0 += __shfl_xor_sync(0xffffffffu, rs0, off);
            rs1 += __shfl_xor_sync(0xffffffffu, rs1, off);
        }
        l0 = l0 * al0 + rs0;
        l1 = l1 * al1 + rs1;
#pragma unroll
        for (int nt = 0; nt < 8; nt++) {
            accO[nt][0] *= al0; accO[nt][1] *= al0;
            accO[nt][2] *= al1; accO[nt][3] *= al1;
        }

        uint32_t ph[4][4], pl[4][4];
#pragma unroll
        for (int kg = 0; kg < 4; kg++) {
            float p00 = sa[2 * kg][0],     p01 = sa[2 * kg][1];
            float p10 = sa[2 * kg][2],     p11 = sa[2 * kg][3];
            float p20 = sa[2 * kg + 1][0], p21 = sa[2 * kg + 1][1];
            float p30 = sa[2 * kg + 1][2], p31 = sa[2 * kg + 1][3];
            ph[kg][0] = pack_bf16(p00, p01);
            ph[kg][1] = pack_bf16(p10, p11);
            ph[kg][2] = pack_bf16(p20, p21);
            ph[kg][3] = pack_bf16(p30, p31);
            __nv_bfloat162 h0 = *(__nv_bfloat162*)&ph[kg][0];
            __nv_bfloat162 h1 = *(__nv_bfloat162*)&ph[kg][1];
            __nv_bfloat162 h2 = *(__nv_bfloat162*)&ph[kg][2];
            __nv_bfloat162 h3 = *(__nv_bfloat162*)&ph[kg][3];
            pl[kg][0] = pack_bf16(p00 - __bfloat162float(h0.x), p01 - __bfloat162float(h0.y));
            pl[kg][1] = pack_bf16(p10 - __bfloat162float(h1.x), p11 - __bfloat162float(h1.y));
            pl[kg][2] = pack_bf16(p20 - __bfloat162float(h2.x), p21 - __bfloat162float(h2.y));
            pl[kg][3] = pack_bf16(p30 - __bfloat162float(h3.x), p31 - __bfloat162float(h3.y));
        }

        const uint32_t vsrc[3] = {uVh, uVl, uVh};
#pragma unroll
        for (int cb = 0; cb < 3; cb++) {
            uint32_t (*pf)[4] = (cb == 2) ? pl : ph;
#pragma unroll
            for (int kg = 0; kg < 4; kg++) {
#pragma unroll
                for (int gg = 0; gg < 4; gg++) {
                    uint32_t bf[4];
                    ldmat4(bf, vsrc[cb] + (uint32_t)(gg * 16 + b_r) * (FSTR * 2) + (kg * 16 + b_c) * 2);
                    mma16816(accO[gg * 2], pf[kg], bf[0], bf[1]);
                    mma16816(accO[gg * 2 + 1], pf[kg], bf[2], bf[3]);
                }
            }
        }
    }

    float inv0 = 1.0f / l0, inv1 = 1.0f / l1;
    int row0 = qi * 64 + wid * 16 + g;
#pragma unroll
    for (int nt = 0; nt < 8; nt++) {
        int col = nt * 8 + t * 2;
        float2 v0 = make_float2(accO[nt][0] * inv0, accO[nt][1] * inv0);
        float2 v1 = make_float2(accO[nt][2] * inv1, accO[nt][3] * inv1);
        *(float2*)&o[headoff + (size_t)row0 * cfg::D + col] = v0;
        *(float2*)&o[headoff + (size_t)(row0 + 8) * cfg::D + col] = v1;
    }
}

// ---------------- layernorm (unbiased std) -------------------------------------
__inline__ __device__ float block_reduce_sum(float val) {
    __shared__ float sbuf[8];
    int lane = threadIdx.x & 31, wid = threadIdx.x >> 5;
#pragma unroll
    for (int o = 16; o; o >>= 1) val += __shfl_xor_sync(0xffffffffu, val, o);
    if (lane == 0) sbuf[wid] = val;
    __syncthreads();
    val = (threadIdx.x < 8) ? sbuf[threadIdx.x] : 0.f;
    if (wid == 0) {
#pragma unroll
        for (int o = 4; o; o >>= 1) val += __shfl_xor_sync(0xffffffffu, val, o);
        if (lane == 0) sbuf[0] = val;
    }
    __syncthreads();
    float r = sbuf[0];
    __syncthreads();
    return r;
}

__global__ void layernorm_kernel(float* __restrict__ h, const float* __restrict__ g,
                                 const float* __restrict__ be) {
    int row = blockIdx.x;
    float* p = h + (size_t)row * cfg::D;
    int d0 = threadIdx.x * 4;
    float4 xv = *(float4*)&p[d0];
    float s = xv.x + xv.y + xv.z + xv.w;
    s = block_reduce_sum(s);
    float mean = s * (1.0f / cfg::D);
    float dx[4] = {xv.x - mean, xv.y - mean, xv.z - mean, xv.w - mean};
    float sq = dx[0] * dx[0] + dx[1] * dx[1] + dx[2] * dx[2] + dx[3] * dx[3];
    sq = block_reduce_sum(sq);
    float stdv = sqrtf(sq / (float)(cfg::D - 1));
    float inv = 1.0f / (stdv + cfg::EPS);
    float4 gg = *(const float4*)&g[d0];
    float4 bb = *(const float4*)&be[d0];
    float4 o;
    o.x = dx[0] * inv * gg.x + bb.x;
    o.y = dx[1] * inv * gg.y + bb.y;
    o.z = dx[2] * inv * gg.z + bb.z;
    o.w = dx[3] * inv * gg.w + bb.w;
    *(float4*)&p[d0] = o;
}

// ---------------- row softmax over V=32000 -------------------------------------
__global__ void softmax_kernel(float* __restrict__ out) {
    int row = blockIdx.x;
    float* p = out + (size_t)row * cfg::V;
    float m = -1e30f, s = 0.f;
    for (int j = threadIdx.x; j < cfg::V; j += 256) {
        float xv = p[j];
        if (xv > m) { s = s * __expf(m - xv) + 1.0f; m = xv; }
        else        { s += __expf(xv - m); }
    }
    __shared__ float sm[256], ss[256];
    sm[threadIdx.x] = m; ss[threadIdx.x] = s;
    __syncthreads();
    for (int off = 128; off; off >>= 1) {
        if (threadIdx.x < off) {
            float m1 = sm[threadIdx.x], s1 = ss[threadIdx.x];
            float m2 = sm[threadIdx.x + off], s2 = ss[threadIdx.x + off];
            float mm = fmaxf(m1, m2);
            sm[threadIdx.x] = mm;
            ss[threadIdx.x] = s1 * __expf(m1 - mm) + s2 * __expf(m2 - mm);
        }
        __syncthreads();
    }
    float mall = sm[0];
    float inv = 1.0f / ss[0];
    for (int j = threadIdx.x; j < cfg::V; j += 256) {
        p[j] = __expf(p[j] - mall) * inv;
    }
}

// ---------------- host orchestration -------------------------------------------
extern "C" void kernel_launch(void* const* d_in, const int* in_sizes, int n_in,
                              void* d_out, int out_size) {
    using namespace cfg;
    const int*   x   = (const int*)d_in[0];
    const float* emb = (const float*)d_in[1];
    const float* Wq  = (const float*)d_in[2];
    const float* bq  = (const float*)d_in[3];
    const float* Wk  = (const float*)d_in[4];
    const float* bk  = (const float*)d_in[5];
    const float* Wv  = (const float*)d_in[6];
    const float* bv  = (const float*)d_in[7];
    const float* Wo  = (const float*)d_in[8];
    const float* bo  = (const float*)d_in[9];
    const float* g1  = (const float*)d_in[10];
    const float* be1 = (const float*)d_in[11];
    const float* W1  = (const float*)d_in[12];
    const float* bf1 = (const float*)d_in[13];
    const float* W2  = (const float*)d_in[14];
    const float* bf2 = (const float*)d_in[15];
    const float* g2  = (const float*)d_in[16];
    const float* be2 = (const float*)d_in[17];
    const float* Wl  = (const float*)d_in[18];
    const float* bl  = (const float*)d_in[19];
    float* out = (float*)d_out;

    float *h, *q, *k, *v, *o, *f;
    cudaGetSymbolAddress((void**)&h, g_h);
    cudaGetSymbolAddress((void**)&q, g_q);
    cudaGetSymbolAddress((void**)&k, g_k);
    cudaGetSymbolAddress((void**)&v, g_v);
    cudaGetSymbolAddress((void**)&o, g_o);
    cudaGetSymbolAddress((void**)&f, g_f);

    __nv_bfloat16 *ah, *al, *wqh, *wql, *wkh, *wkl, *wvh, *wvl, *woh, *wol;
    __nv_bfloat16 *w1h, *w1l, *w2h, *w2l, *wlh;
    cudaGetSymbolAddress((void**)&ah, g_ah);
    cudaGetSymbolAddress((void**)&al, g_al);
    cudaGetSymbolAddress((void**)&wqh, g_wqh); cudaGetSymbolAddress((void**)&wql, g_wql);
    cudaGetSymbolAddress((void**)&wkh, g_wkh); cudaGetSymbolAddress((void**)&wkl, g_wkl);
    cudaGetSymbolAddress((void**)&wvh, g_wvh); cudaGetSymbolAddress((void**)&wvl, g_wvl);
    cudaGetSymbolAddress((void**)&woh, g_woh); cudaGetSymbolAddress((void**)&wol, g_wol);
    cudaGetSymbolAddress((void**)&w1h, g_w1h); cudaGetSymbolAddress((void**)&w1l, g_w1l);
    cudaGetSymbolAddress((void**)&w2h, g_w2h); cudaGetSymbolAddress((void**)&w2l, g_w2l);
    cudaGetSymbolAddress((void**)&wlh, g_wlh);

    cudaFuncSetAttribute(gemm_hmma<false>, cudaFuncAttributeMaxDynamicSharedMemorySize, GEMM_SMEM);
    cudaFuncSetAttribute(gemm_hmma<true>,  cudaFuncAttributeMaxDynamicSharedMemorySize, GEMM_SMEM);
    cudaFuncSetAttribute(gemm_half, cudaFuncAttributeMaxDynamicSharedMemorySize, HALF_SMEM);

    dim3 tb(32, 32);
    tsplit_kernel<<<dim3(D / 32, D / 32), tb>>>(Wq, wqh, wql, D, D);
    tsplit_kernel<<<dim3(D / 32, D / 32), tb>>>(Wk, wkh, wkl, D, D);
    tsplit_kernel<<<dim3(D / 32, D / 32), tb>>>(Wv, wvh, wvl, D, D);
    tsplit_kernel<<<dim3(D / 32, D / 32), tb>>>(Wo, woh, wol, D, D);
    tsplit_kernel<<<dim3(F / 32, D / 32), tb>>>(W1, w1h, w1l, D, F);
    tsplit_kernel<<<dim3(D / 32, F / 32), tb>>>(W2, w2h, w2l, F, D);
    thalf_kernel<<<dim3(V / 32, D / 32), tb>>>(Wl, (__half*)wlh, D, V);

    embed_kernel<<<M, 256>>>(x, emb, h);
    split_kernel<<<(M * D / 4 + 255) / 256, 256>>>(h, ah, al, M * D / 4);

    gemm_hmma<false><<<dim3(M / 128, D / 256), 512, GEMM_SMEM>>>(ah, al, wqh, wql, bq, q, D, D);
    gemm_hmma<false><<<dim3(M / 128, D / 256), 512, GEMM_SMEM>>>(ah, al, wkh, wkl, bk, k, D, D);
    gemm_hmma<false><<<dim3(M / 128, D / 256), 512, GEMM_SMEM>>>(ah, al, wvh, wvl, bv, v, D, D);

    flash_hmma<<<dim3(T / 64, H, B), 128>>>(q, k, v, o);

    split_kernel<<<(M * D / 4 + 255) / 256, 256>>>(o, ah, al, M * D / 4);
    gemm_hmma<false><<<dim3(M / 128, D / 256), 512, GEMM_SMEM>>>(ah, al, woh, wol, bo, h, D, D);
    layernorm_kernel<<<M, 256>>>(h, g1, be1);

    split_kernel<<<(M * D / 4 + 255) / 256, 256>>>(h, ah, al, M * D / 4);
    gemm_hmma<true><<<dim3(M / 128, F / 256), 512, GEMM_SMEM>>>(ah, al, w1h, w1l, bf1, f, F, D);

    split_kernel<<<((size_t)M * F / 4 + 255) / 256, 256>>>(f, ah, al, M * F / 4);
    gemm_hmma<false><<<dim3(M / 128, D / 256), 512, GEMM_SMEM>>>(ah, al, w2h, w2l, bf2, o, D, F);
    layernorm_kernel<<<M, 256>>>(o, g2, be2);

    tohalf_kernel<<<(M * D / 4 + 255) / 256, 256>>>(o, (__half*)ah, M * D / 4);
    gemm_half<<<dim3(M / 128, V / 256), 512, HALF_SMEM>>>((__half*)ah, (__half*)wlh, bl, out, V, D);

    softmax_kernel<<<M, 256>>>(out);
}

// round 7
// speedup vs baseline: 4.3105x; 1.3759x over previous
#include <cuda_runtime.h>
#include <cuda_bf16.h>
#include <cuda_fp16.h>
#include <math.h>
#include <stdint.h>

// ---------------- problem constants ----------------
namespace cfg {
constexpr int B = 2, T = 2048, D = 1024, H = 16, HD = 64, F = 4096, V = 32000;
constexpr int M = B * T;
constexpr float EPS = 1e-6f;
}

// ---------------- scratch ----------------------------------------------------
__device__ float g_h[cfg::M * cfg::D];     // fp32 staging (Wo out, FFN2 out)
__device__ float g_q[cfg::M * cfg::D];
__device__ float g_k[cfg::M * cfg::D];
__device__ float g_v[cfg::M * cfg::D];
__device__ float g_o[cfg::M * cfg::D];

__device__ __half g_x16[(size_t)cfg::M * cfg::F];   // fp16 activations (big: FFN1 out)
__device__ __half g_h16[cfg::M * cfg::D];           // embed out / LN1 out
__device__ __half g_o16[cfg::M * cfg::D];           // flash out / LN2 out

__device__ __half g_wq[cfg::D * cfg::D], g_wk[cfg::D * cfg::D];
__device__ __half g_wv[cfg::D * cfg::D], g_wo[cfg::D * cfg::D];
__device__ __half g_w1[(size_t)cfg::D * cfg::F], g_w2[(size_t)cfg::D * cfg::F];
__device__ __half g_wl[(size_t)cfg::V * cfg::D];

// ---------------- PTX helpers -------------------------------------------------
__device__ __forceinline__ uint32_t smem_u32(const void* p) {
    uint32_t a;
    asm("{ .reg .u64 t; cvta.to.shared.u64 t, %1; cvt.u32.u64 %0, t; }" : "=r"(a) : "l"(p));
    return a;
}
__device__ __forceinline__ void cp16(uint32_t dst, const void* src) {
    asm volatile("cp.async.cg.shared.global [%0], [%1], 16;" :: "r"(dst), "l"(src));
}
__device__ __forceinline__ void cp_commit() {
    asm volatile("cp.async.commit_group;" ::: "memory");
}
template <int N>
__device__ __forceinline__ void cp_wait() {
    asm volatile("cp.async.wait_group %0;" :: "n"(N) : "memory");
}
__device__ __forceinline__ void ldmat4(uint32_t* r, uint32_t addr) {
    asm volatile("ldmatrix.sync.aligned.m8n8.x4.shared.b16 {%0,%1,%2,%3}, [%4];"
                 : "=r"(r[0]), "=r"(r[1]), "=r"(r[2]), "=r"(r[3]) : "r"(addr));
}
__device__ __forceinline__ void mma16816(float* c, const uint32_t* a, uint32_t b0, uint32_t b1) {
    asm volatile(
        "mma.sync.aligned.m16n8k16.row.col.f32.bf16.bf16.f32 "
        "{%0,%1,%2,%3}, {%4,%5,%6,%7}, {%8,%9}, {%0,%1,%2,%3};"
        : "+f"(c[0]), "+f"(c[1]), "+f"(c[2]), "+f"(c[3])
        : "r"(a[0]), "r"(a[1]), "r"(a[2]), "r"(a[3]), "r"(b0), "r"(b1));
}
__device__ __forceinline__ void mma16816h(float* c, const uint32_t* a, uint32_t b0, uint32_t b1) {
    asm volatile(
        "mma.sync.aligned.m16n8k16.row.col.f32.f16.f16.f32 "
        "{%0,%1,%2,%3}, {%4,%5,%6,%7}, {%8,%9}, {%0,%1,%2,%3};"
        : "+f"(c[0]), "+f"(c[1]), "+f"(c[2]), "+f"(c[3])
        : "r"(a[0]), "r"(a[1]), "r"(a[2]), "r"(a[3]), "r"(b0), "r"(b1));
}
__device__ __forceinline__ uint32_t pack_bf16(float x, float y) {
    __nv_bfloat162 t = __floats2bfloat162_rn(x, y);
    return *(uint32_t*)&t;
}

// ---------------- fp16 single-product GEMM (all weight GEMMs) ------------------
// C[M,N] = A@B^T + bias. A [M,K] fp16, B [N,K] fp16. CTA 128x256, BK=32,
// 512 thr (16 warps 2x8), 4-stage cp.async, 80B stride.
static constexpr uint32_t HA_BYTES = 128 * 80;
static constexpr uint32_t HB_BYTES = 256 * 80;
static constexpr uint32_t HSTAGE = HA_BYTES + HB_BYTES;
static constexpr uint32_t HALF_SMEM = 4 * HSTAGE;   // 122880

template <bool RELU, bool HALFOUT>
__global__ __launch_bounds__(512, 1) void gemm_half(
    const __half* __restrict__ A, const __half* __restrict__ B,
    const float* __restrict__ bias, void* __restrict__ Cout, int Nd, int Kd) {
    extern __shared__ char smem[];
    const uint32_t sb = smem_u32(smem);
    const int tid = threadIdx.x;
    const int wid = tid >> 5, lane = tid & 31;
    const int wm = wid & 1, wn = wid >> 1;
    const int bm = blockIdx.x * 128;
    const int bn = blockIdx.y * 256;
    const int NC = Kd >> 5;

    const int arow = tid >> 2, aseg = tid & 3;

    auto issue = [&](int c) {
        const int k0 = c << 5;
        const uint32_t base = sb + (c & 3) * HSTAGE;
        cp16(base + arow * 80 + aseg * 16, A + (size_t)(bm + arow) * Kd + k0 + aseg * 8);
#pragma unroll
        for (int it = 0; it < 2; it++) {
            int i = tid + it * 512;
            int br = i >> 2, bs = i & 3;
            cp16(base + HA_BYTES + br * 80 + bs * 16,
                 B + (size_t)(bn + br) * Kd + k0 + bs * 8);
        }
    };

    issue(0); cp_commit();
    issue(1); cp_commit();
    issue(2); cp_commit();

    float acc[4][4][4];
#pragma unroll
    for (int i = 0; i < 4; i++)
#pragma unroll
        for (int j = 0; j < 4; j++)
#pragma unroll
            for (int r = 0; r < 4; r++) acc[i][j][r] = 0.f;

    const int a_r = lane & 15;
    const int a_c = (lane >> 4) << 3;
    const int b_r = (lane & 7) + ((lane >> 4) << 3);
    const int b_c = ((lane >> 3) & 1) << 3;

    for (int c = 0; c < NC; c++) {
        cp_wait<2>();
        __syncthreads();
        if (c + 3 < NC) issue(c + 3);
        cp_commit();

        const uint32_t sA = sb + (c & 3) * HSTAGE;
        const uint32_t sB = sA + HA_BYTES;
#pragma unroll
        for (int kk = 0; kk < 2; kk++) {
            uint32_t a[4][4], b[2][4];
#pragma unroll
            for (int mt = 0; mt < 4; mt++)
                ldmat4(a[mt], sA + (uint32_t)(wm * 64 + mt * 16 + a_r) * 80
                              + (uint32_t)(kk * 16 + a_c) * 2);
#pragma unroll
            for (int g = 0; g < 2; g++)
                ldmat4(b[g], sB + (uint32_t)(wn * 32 + g * 16 + b_r) * 80
                             + (uint32_t)(kk * 16 + b_c) * 2);
#pragma unroll
            for (int mt = 0; mt < 4; mt++)
#pragma unroll
                for (int nt = 0; nt < 4; nt++)
                    mma16816h(acc[mt][nt], a[mt],
                              b[nt >> 1][(nt & 1) * 2], b[nt >> 1][(nt & 1) * 2 + 1]);
        }
    }

    const int g = lane >> 2, t = lane & 3;
#pragma unroll
    for (int mt = 0; mt < 4; mt++) {
#pragma unroll
        for (int nt = 0; nt < 4; nt++) {
            int row0 = bm + wm * 64 + mt * 16 + g;
            int col = bn + wn * 32 + nt * 8 + t * 2;
            float bx = bias[col], by = bias[col + 1];
            float2 v0, v1;
            v0.x = acc[mt][nt][0] + bx; v0.y = acc[mt][nt][1] + by;
            v1.x = acc[mt][nt][2] + bx; v1.y = acc[mt][nt][3] + by;
            if (RELU) {
                v0.x = fmaxf(v0.x, 0.f); v0.y = fmaxf(v0.y, 0.f);
                v1.x = fmaxf(v1.x, 0.f); v1.y = fmaxf(v1.y, 0.f);
            }
            if (HALFOUT) {
                __half* C = (__half*)Cout;
                *(__half2*)&C[(size_t)row0 * Nd + col] = __floats2half2_rn(v0.x, v0.y);
                *(__half2*)&C[(size_t)(row0 + 8) * Nd + col] = __floats2half2_rn(v1.x, v1.y);
            } else {
                float* C = (float*)Cout;
                *(float2*)&C[(size_t)row0 * Nd + col] = v0;
                *(float2*)&C[(size_t)(row0 + 8) * Nd + col] = v1;
            }
        }
    }
}

// transpose to fp16: W[K,N] -> [N,K] half
__global__ void thalf_kernel(const float* __restrict__ W, __half* __restrict__ out,
                             int K, int N) {
    __shared__ float s[32][33];
    int n = blockIdx.x * 32 + threadIdx.x;
    int k = blockIdx.y * 32 + threadIdx.y;
    s[threadIdx.y][threadIdx.x] = W[(size_t)k * N + n];
    __syncthreads();
    int no = blockIdx.x * 32 + threadIdx.y;
    int ko = blockIdx.y * 32 + threadIdx.x;
    out[(size_t)no * K + ko] = __float2half_rn(s[threadIdx.x][threadIdx.y]);
}

// ---------------- embed + positional encoding -> fp16 --------------------------
__global__ void embed_kernel(const int* __restrict__ x, const float* __restrict__ emb,
                             __half* __restrict__ h16) {
    int row = blockIdx.x;
    int t = row & (cfg::T - 1);
    int tok = x[row];
    const float* e = emb + (size_t)tok * cfg::D;
    int d0 = threadIdx.x * 4;
    float4 ev = *(const float4*)&e[d0];
    const float cfac = -0.017988946039015984f;
    int i0 = d0 >> 1;
    float f0 = expf((float)i0 * cfac);
    float f1 = expf((float)(i0 + 1) * cfac);
    float a0 = (float)t * f0, a1 = (float)t * f1;
    __half2 p0 = __floats2half2_rn(ev.x + sinf(a0), ev.y + cosf(a0));
    __half2 p1 = __floats2half2_rn(ev.z + sinf(a1), ev.w + cosf(a1));
    uint2 pk = make_uint2(*(uint32_t*)&p0, *(uint32_t*)&p1);
    *(uint2*)&h16[(size_t)row * cfg::D + d0] = pk;
}

// ---------------- HMMA flash attention (bf16x3, causal), fp16 output ----------
static constexpr int FSTR = 72;

__global__ __launch_bounds__(128) void flash_hmma(
    const float* __restrict__ q, const float* __restrict__ k,
    const float* __restrict__ v, __half* __restrict__ o16) {
    __shared__ __nv_bfloat16 sQh[64 * FSTR], sQl[64 * FSTR];
    __shared__ __nv_bfloat16 sKh[64 * FSTR], sKl[64 * FSTR];
    __shared__ __nv_bfloat16 sVh[64 * FSTR], sVl[64 * FSTR];

    const int qi = gridDim.x - 1 - blockIdx.x;
    const int h = blockIdx.y, b = blockIdx.z;
    const int tid = threadIdx.x;
    const int wid = tid >> 5, lane = tid & 31;
    const size_t headoff = ((size_t)b * cfg::T) * cfg::D + (size_t)h * cfg::HD;

    const uint32_t uQh = smem_u32(sQh), uQl = smem_u32(sQl);
    const uint32_t uKh = smem_u32(sKh), uKl = smem_u32(sKl);
    const uint32_t uVh = smem_u32(sVh), uVl = smem_u32(sVl);

    const int a_r = lane & 15;
    const int a_c = (lane >> 4) << 3;
    const int b_r = (lane & 7) + ((lane >> 4) << 3);
    const int b_c = ((lane >> 3) & 1) << 3;
    const int g = lane >> 2, t = lane & 3;

#pragma unroll
    for (int it = 0; it < 8; it++) {
        int idx = tid + it * 128;
        int r = idx >> 4, dq = (idx & 15) * 4;
        float4 tv = *(const float4*)&q[headoff + (size_t)(qi * 64 + r) * cfg::D + dq];
        uint32_t h01 = pack_bf16(tv.x, tv.y);
        uint32_t h23 = pack_bf16(tv.z, tv.w);
        *(uint2*)&sQh[r * FSTR + dq] = make_uint2(h01, h23);
        __nv_bfloat162 hh0 = *(__nv_bfloat162*)&h01;
        __nv_bfloat162 hh1 = *(__nv_bfloat162*)&h23;
        uint32_t l01 = pack_bf16(tv.x - __bfloat162float(hh0.x), tv.y - __bfloat162float(hh0.y));
        uint32_t l23 = pack_bf16(tv.z - __bfloat162float(hh1.x), tv.w - __bfloat162float(hh1.y));
        *(uint2*)&sQl[r * FSTR + dq] = make_uint2(l01, l23);
    }

    float accO[8][4];
#pragma unroll
    for (int i = 0; i < 8; i++)
#pragma unroll
        for (int j = 0; j < 4; j++) accO[i][j] = 0.f;
    float m0 = -1e30f, m1 = -1e30f, l0 = 0.f, l1 = 0.f;

    for (int kt = 0; kt <= qi; kt++) {
        __syncthreads();
#pragma unroll
        for (int it = 0; it < 8; it++) {
            int idx = tid + it * 128;
            int r = idx >> 4, dq = (idx & 15) * 4;
            float4 tv = *(const float4*)&k[headoff + (size_t)(kt * 64 + r) * cfg::D + dq];
            uint32_t h01 = pack_bf16(tv.x, tv.y);
            uint32_t h23 = pack_bf16(tv.z, tv.w);
            *(uint2*)&sKh[r * FSTR + dq] = make_uint2(h01, h23);
            __nv_bfloat162 hh0 = *(__nv_bfloat162*)&h01;
            __nv_bfloat162 hh1 = *(__nv_bfloat162*)&h23;
            uint32_t l01 = pack_bf16(tv.x - __bfloat162float(hh0.x), tv.y - __bfloat162float(hh0.y));
            uint32_t l23 = pack_bf16(tv.z - __bfloat162float(hh1.x), tv.w - __bfloat162float(hh1.y));
            *(uint2*)&sKl[r * FSTR + dq] = make_uint2(l01, l23);

            float4 vv = *(const float4*)&v[headoff + (size_t)(kt * 64 + r) * cfg::D + dq];
            float vals[4] = {vv.x, vv.y, vv.z, vv.w};
#pragma unroll
            for (int j = 0; j < 4; j++) {
                __nv_bfloat16 hb = __float2bfloat16_rn(vals[j]);
                sVh[(dq + j) * FSTR + r] = hb;
                sVl[(dq + j) * FSTR + r] = __float2bfloat16_rn(vals[j] - __bfloat162float(hb));
            }
        }
        __syncthreads();

        float sa[8][4];
#pragma unroll
        for (int i = 0; i < 8; i++)
#pragma unroll
            for (int j = 0; j < 4; j++) sa[i][j] = 0.f;

        const uint32_t qsrc[3] = {uQh, uQh, uQl};
        const uint32_t ksrc[3] = {uKh, uKl, uKh};
#pragma unroll
        for (int cb = 0; cb < 3; cb++) {
#pragma unroll
            for (int kg = 0; kg < 4; kg++) {
                uint32_t af[4];
                ldmat4(af, qsrc[cb] + (uint32_t)(wid * 16 + a_r) * (FSTR * 2) + (kg * 16 + a_c) * 2);
#pragma unroll
                for (int gg = 0; gg < 4; gg++) {
                    uint32_t bf[4];
                    ldmat4(bf, ksrc[cb] + (uint32_t)(gg * 16 + b_r) * (FSTR * 2) + (kg * 16 + b_c) * 2);
                    mma16816(sa[gg * 2], af, bf[0], bf[1]);
                    mma16816(sa[gg * 2 + 1], af, bf[2], bf[3]);
                }
            }
        }

        const bool diag = (kt == qi);
#pragma unroll
        for (int nt = 0; nt < 8; nt++) {
            int c0 = nt * 8 + t * 2;
            sa[nt][0] *= 0.125f; sa[nt][1] *= 0.125f;
            sa[nt][2] *= 0.125f; sa[nt][3] *= 0.125f;
            if (diag) {
                int r0 = wid * 16 + g, r1 = r0 + 8;
                if (c0 > r0)     sa[nt][0] = -1e30f;
                if (c0 + 1 > r0) sa[nt][1] = -1e30f;
                if (c0 > r1)     sa[nt][2] = -1e30f;
                if (c0 + 1 > r1) sa[nt][3] = -1e30f;
            }
        }

        float mt0 = -1e30f, mt1 = -1e30f;
#pragma unroll
        for (int nt = 0; nt < 8; nt++) {
            mt0 = fmaxf(mt0, fmaxf(sa[nt][0], sa[nt][1]));
            mt1 = fmaxf(mt1, fmaxf(sa[nt][2], sa[nt][3]));
        }
#pragma unroll
        for (int off = 1; off <= 2; off <<= 1) {
            mt0 = fmaxf(mt0, __shfl_xor_sync(0xffffffffu, mt0, off));
            mt1 = fmaxf(mt1, __shfl_xor_sync(0xffffffffu, mt1, off));
        }
        float mn0 = fmaxf(m0, mt0), mn1 = fmaxf(m1, mt1);
        float al0 = __expf(m0 - mn0), al1 = __expf(m1 - mn1);
        m0 = mn0; m1 = mn1;

        float rs0 = 0.f, rs1 = 0.f;
#pragma unroll
        for (int nt = 0; nt < 8; nt++) {
            sa[nt][0] = __expf(sa[nt][0] - mn0);
            sa[nt][1] = __expf(sa[nt][1] - mn0);
            sa[nt][2] = __expf(sa[nt][2] - mn1);
            sa[nt][3] = __expf(sa[nt][3] - mn1);
            rs0 += sa[nt][0] + sa[nt][1];
            rs1 += sa[nt][2] + sa[nt][3];
        }
#pragma unroll
        for (int off = 1; off <= 2; off <<= 1) {
            rs0 += __shfl_xor_sync(0xffffffffu, rs0, off);
            rs1 += __shfl_xor_sync(0xffffffffu, rs1, off);
        }
        l0 = l0 * al0 + rs0;
        l1 = l1 * al1 + rs1;
#pragma unroll
        for (int nt = 0; nt < 8; nt++) {
            accO[nt][0] *= al0; accO[nt][1] *= al0;
            accO[nt][2] *= al1; accO[nt][3] *= al1;
        }

        uint32_t ph[4][4], pl[4][4];
#pragma unroll
        for (int kg = 0; kg < 4; kg++) {
            float p00 = sa[2 * kg][0],     p01 = sa[2 * kg][1];
            float p10 = sa[2 * kg][2],     p11 = sa[2 * kg][3];
            float p20 = sa[2 * kg + 1][0], p21 = sa[2 * kg + 1][1];
            float p30 = sa[2 * kg + 1][2], p31 = sa[2 * kg + 1][3];
            ph[kg][0] = pack_bf16(p00, p01);
            ph[kg][1] = pack_bf16(p10, p11);
            ph[kg][2] = pack_bf16(p20, p21);
            ph[kg][3] = pack_bf16(p30, p31);
            __nv_bfloat162 h0 = *(__nv_bfloat162*)&ph[kg][0];
            __nv_bfloat162 h1 = *(__nv_bfloat162*)&ph[kg][1];
            __nv_bfloat162 h2 = *(__nv_bfloat162*)&ph[kg][2];
            __nv_bfloat162 h3 = *(__nv_bfloat162*)&ph[kg][3];
            pl[kg][0] = pack_bf16(p00 - __bfloat162float(h0.x), p01 - __bfloat162float(h0.y));
            pl[kg][1] = pack_bf16(p10 - __bfloat162float(h1.x), p11 - __bfloat162float(h1.y));
            pl[kg][2] = pack_bf16(p20 - __bfloat162float(h2.x), p21 - __bfloat162float(h2.y));
            pl[kg][3] = pack_bf16(p30 - __bfloat162float(h3.x), p31 - __bfloat162float(h3.y));
        }

        const uint32_t vsrc[3] = {uVh, uVl, uVh};
#pragma unroll
        for (int cb = 0; cb < 3; cb++) {
            uint32_t (*pf)[4] = (cb == 2) ? pl : ph;
#pragma unroll
            for (int kg = 0; kg < 4; kg++) {
#pragma unroll
                for (int gg = 0; gg < 4; gg++) {
                    uint32_t bf[4];
                    ldmat4(bf, vsrc[cb] + (uint32_t)(gg * 16 + b_r) * (FSTR * 2) + (kg * 16 + b_c) * 2);
                    mma16816(accO[gg * 2], pf[kg], bf[0], bf[1]);
                    mma16816(accO[gg * 2 + 1], pf[kg], bf[2], bf[3]);
                }
            }
        }
    }

    float inv0 = 1.0f / l0, inv1 = 1.0f / l1;
    int row0 = qi * 64 + wid * 16 + g;
#pragma unroll
    for (int nt = 0; nt < 8; nt++) {
        int col = nt * 8 + t * 2;
        *(__half2*)&o16[headoff + (size_t)row0 * cfg::D + col] =
            __floats2half2_rn(accO[nt][0] * inv0, accO[nt][1] * inv0);
        *(__half2*)&o16[headoff + (size_t)(row0 + 8) * cfg::D + col] =
            __floats2half2_rn(accO[nt][2] * inv1, accO[nt][3] * inv1);
    }
}

// ---------------- layernorm (unbiased std), fp32 in -> fp16 out ----------------
__inline__ __device__ float block_reduce_sum(float val) {
    __shared__ float sbuf[8];
    int lane = threadIdx.x & 31, wid = threadIdx.x >> 5;
#pragma unroll
    for (int o = 16; o; o >>= 1) val += __shfl_xor_sync(0xffffffffu, val, o);
    if (lane == 0) sbuf[wid] = val;
    __syncthreads();
    val = (threadIdx.x < 8) ? sbuf[threadIdx.x] : 0.f;
    if (wid == 0) {
#pragma unroll
        for (int o = 4; o; o >>= 1) val += __shfl_xor_sync(0xffffffffu, val, o);
        if (lane == 0) sbuf[0] = val;
    }
    __syncthreads();
    float r = sbuf[0];
    __syncthreads();
    return r;
}

__global__ void layernorm_kernel(const float* __restrict__ in, __half* __restrict__ out16,
                                 const float* __restrict__ g, const float* __restrict__ be) {
    int row = blockIdx.x;
    const float* p = in + (size_t)row * cfg::D;
    int d0 = threadIdx.x * 4;
    float4 xv = *(const float4*)&p[d0];
    float s = xv.x + xv.y + xv.z + xv.w;
    s = block_reduce_sum(s);
    float mean = s * (1.0f / cfg::D);
    float dx[4] = {xv.x - mean, xv.y - mean, xv.z - mean, xv.w - mean};
    float sq = dx[0] * dx[0] + dx[1] * dx[1] + dx[2] * dx[2] + dx[3] * dx[3];
    sq = block_reduce_sum(sq);
    float stdv = sqrtf(sq / (float)(cfg::D - 1));
    float inv = 1.0f / (stdv + cfg::EPS);
    float4 gg = *(const float4*)&g[d0];
    float4 bb = *(const float4*)&be[d0];
    __half2 p0 = __floats2half2_rn(dx[0] * inv * gg.x + bb.x, dx[1] * inv * gg.y + bb.y);
    __half2 p1 = __floats2half2_rn(dx[2] * inv * gg.z + bb.z, dx[3] * inv * gg.w + bb.w);
    uint2 pk = make_uint2(*(uint32_t*)&p0, *(uint32_t*)&p1);
    *(uint2*)&out16[(size_t)row * cfg::D + d0] = pk;
}

// ---------------- row softmax over V=32000 -------------------------------------
__global__ void softmax_kernel(float* __restrict__ out) {
    int row = blockIdx.x;
    float* p = out + (size_t)row * cfg::V;
    float m = -1e30f, s = 0.f;
    for (int j = threadIdx.x; j < cfg::V; j += 256) {
        float xv = p[j];
        if (xv > m) { s = s * __expf(m - xv) + 1.0f; m = xv; }
        else        { s += __expf(xv - m); }
    }
    __shared__ float sm[256], ss[256];
    sm[threadIdx.x] = m; ss[threadIdx.x] = s;
    __syncthreads();
    for (int off = 128; off; off >>= 1) {
        if (threadIdx.x < off) {
            float m1 = sm[threadIdx.x], s1 = ss[threadIdx.x];
            float m2 = sm[threadIdx.x + off], s2 = ss[threadIdx.x + off];
            float mm = fmaxf(m1, m2);
            sm[threadIdx.x] = mm;
            ss[threadIdx.x] = s1 * __expf(m1 - mm) + s2 * __expf(m2 - mm);
        }
        __syncthreads();
    }
    float mall = sm[0];
    float inv = 1.0f / ss[0];
    for (int j = threadIdx.x; j < cfg::V; j += 256) {
        p[j] = __expf(p[j] - mall) * inv;
    }
}

// ---------------- host orchestration -------------------------------------------
extern "C" void kernel_launch(void* const* d_in, const int* in_sizes, int n_in,
                              void* d_out, int out_size) {
    using namespace cfg;
    const int*   x   = (const int*)d_in[0];
    const float* emb = (const float*)d_in[1];
    const float* Wq  = (const float*)d_in[2];
    const float* bq  = (const float*)d_in[3];
    const float* Wk  = (const float*)d_in[4];
    const float* bk  = (const float*)d_in[5];
    const float* Wv  = (const float*)d_in[6];
    const float* bv  = (const float*)d_in[7];
    const float* Wo  = (const float*)d_in[8];
    const float* bo  = (const float*)d_in[9];
    const float* g1  = (const float*)d_in[10];
    const float* be1 = (const float*)d_in[11];
    const float* W1  = (const float*)d_in[12];
    const float* bf1 = (const float*)d_in[13];
    const float* W2  = (const float*)d_in[14];
    const float* bf2 = (const float*)d_in[15];
    const float* g2  = (const float*)d_in[16];
    const float* be2 = (const float*)d_in[17];
    const float* Wl  = (const float*)d_in[18];
    const float* bl  = (const float*)d_in[19];
    float* out = (float*)d_out;

    float *h, *q, *k, *v, *o;
    cudaGetSymbolAddress((void**)&h, g_h);
    cudaGetSymbolAddress((void**)&q, g_q);
    cudaGetSymbolAddress((void**)&k, g_k);
    cudaGetSymbolAddress((void**)&v, g_v);
    cudaGetSymbolAddress((void**)&o, g_o);

    __half *x16, *h16, *o16, *wq, *wk, *wv, *wo, *w1, *w2, *wl;
    cudaGetSymbolAddress((void**)&x16, g_x16);
    cudaGetSymbolAddress((void**)&h16, g_h16);
    cudaGetSymbolAddress((void**)&o16, g_o16);
    cudaGetSymbolAddress((void**)&wq, g_wq);
    cudaGetSymbolAddress((void**)&wk, g_wk);
    cudaGetSymbolAddress((void**)&wv, g_wv);
    cudaGetSymbolAddress((void**)&wo, g_wo);
    cudaGetSymbolAddress((void**)&w1, g_w1);
    cudaGetSymbolAddress((void**)&w2, g_w2);
    cudaGetSymbolAddress((void**)&wl, g_wl);

    cudaFuncSetAttribute((const void*)gemm_half<false, false>,
                         cudaFuncAttributeMaxDynamicSharedMemorySize, HALF_SMEM);
    cudaFuncSetAttribute((const void*)gemm_half<true, true>,
                         cudaFuncAttributeMaxDynamicSharedMemorySize, HALF_SMEM);
    cudaFuncSetAttribute((const void*)gemm_half<false, true>,
                         cudaFuncAttributeMaxDynamicSharedMemorySize, HALF_SMEM);

    dim3 tb(32, 32);
    embed_kernel<<<M, 256>>>(x, emb, h16);                               // 0
    thalf_kernel<<<dim3(D / 32, D / 32), tb>>>(Wq, wq, D, D);            // 1
    thalf_kernel<<<dim3(D / 32, D / 32), tb>>>(Wk, wk, D, D);            // 2
    thalf_kernel<<<dim3(D / 32, D / 32), tb>>>(Wv, wv, D, D);            // 3
    thalf_kernel<<<dim3(D / 32, D / 32), tb>>>(Wo, wo, D, D);            // 4
    gemm_half<false, false><<<dim3(M / 128, D / 256), 512, HALF_SMEM>>>( // 5 (ncu)
        h16, wq, bq, q, D, D);
    gemm_half<false, false><<<dim3(M / 128, D / 256), 512, HALF_SMEM>>>(h16, wk, bk, k, D, D);
    gemm_half<false, false><<<dim3(M / 128, D / 256), 512, HALF_SMEM>>>(h16, wv, bv, v, D, D);

    flash_hmma<<<dim3(T / 64, H, B), 128>>>(q, k, v, o16);

    gemm_half<false, false><<<dim3(M / 128, D / 256), 512, HALF_SMEM>>>(o16, wo, bo, h, D, D);
    layernorm_kernel<<<M, 256>>>(h, h16, g1, be1);

    thalf_kernel<<<dim3(F / 32, D / 32), tb>>>(W1, w1, D, F);
    gemm_half<true, true><<<dim3(M / 128, F / 256), 512, HALF_SMEM>>>(h16, w1, bf1, x16, F, D);

    thalf_kernel<<<dim3(D / 32, F / 32), tb>>>(W2, w2, F, D);
    gemm_half<false, false><<<dim3(M / 128, D / 256), 512, HALF_SMEM>>>(x16, w2, bf2, o, D, F);
    layernorm_kernel<<<M, 256>>>(o, o16, g2, be2);

    thalf_kernel<<<dim3(V / 32, D / 32), tb>>>(Wl, wl, D, V);
    gemm_half<false, false><<<dim3(M / 128, V / 256), 512, HALF_SMEM>>>(o16, wl, bl, out, V, D);

    softmax_kernel<<<M, 256>>>(out);
}

// round 10
// speedup vs baseline: 5.1088x; 1.1852x over previous
#include <cuda_runtime.h>
#include <cuda_fp16.h>
#include <math.h>
#include <stdint.h>

// ---------------- problem constants ----------------
namespace cfg {
constexpr int B = 2, T = 2048, D = 1024, H = 16, HD = 64, F = 4096, V = 32000;
constexpr int M = B * T;
constexpr float EPS = 1e-6f;
}

// ---------------- scratch ----------------------------------------------------
__device__ float g_h[cfg::M * cfg::D];     // fp32 staging (Wo out)
__device__ float g_o[cfg::M * cfg::D];     // fp32 staging (FFN2 out)

__device__ __half g_x16[(size_t)cfg::M * cfg::F];   // FFN1 out
__device__ __half g_h16[cfg::M * cfg::D];           // embed out / LN1 out
__device__ __half g_o16[cfg::M * cfg::D];           // flash out / LN2 out
__device__ __half g_q16[cfg::M * cfg::D];
__device__ __half g_k16[cfg::M * cfg::D];
__device__ __half g_v16[cfg::M * cfg::D];

__device__ __half g_wq[cfg::D * cfg::D], g_wk[cfg::D * cfg::D];
__device__ __half g_wv[cfg::D * cfg::D], g_wo[cfg::D * cfg::D];
__device__ __half g_w1[(size_t)cfg::D * cfg::F], g_w2[(size_t)cfg::D * cfg::F];
__device__ __half g_wl[(size_t)cfg::V * cfg::D];

// ---------------- PTX helpers -------------------------------------------------
__device__ __forceinline__ uint32_t smem_u32(const void* p) {
    uint32_t a;
    asm("{ .reg .u64 t; cvta.to.shared.u64 t, %1; cvt.u32.u64 %0, t; }" : "=r"(a) : "l"(p));
    return a;
}
__device__ __forceinline__ void cp16(uint32_t dst, const void* src) {
    asm volatile("cp.async.cg.shared.global [%0], [%1], 16;" :: "r"(dst), "l"(src));
}
__device__ __forceinline__ void cp_commit() {
    asm volatile("cp.async.commit_group;" ::: "memory");
}
template <int N>
__device__ __forceinline__ void cp_wait() {
    asm volatile("cp.async.wait_group %0;" :: "n"(N) : "memory");
}
__device__ __forceinline__ void ldmat4(uint32_t* r, uint32_t addr) {
    asm volatile("ldmatrix.sync.aligned.m8n8.x4.shared.b16 {%0,%1,%2,%3}, [%4];"
                 : "=r"(r[0]), "=r"(r[1]), "=r"(r[2]), "=r"(r[3]) : "r"(addr));
}
__device__ __forceinline__ void ldmat4t(uint32_t* r, uint32_t addr) {
    asm volatile("ldmatrix.sync.aligned.m8n8.x4.trans.shared.b16 {%0,%1,%2,%3}, [%4];"
                 : "=r"(r[0]), "=r"(r[1]), "=r"(r[2]), "=r"(r[3]) : "r"(addr));
}
__device__ __forceinline__ void mma16816h(float* c, const uint32_t* a, uint32_t b0, uint32_t b1) {
    asm volatile(
        "mma.sync.aligned.m16n8k16.row.col.f32.f16.f16.f32 "
        "{%0,%1,%2,%3}, {%4,%5,%6,%7}, {%8,%9}, {%0,%1,%2,%3};"
        : "+f"(c[0]), "+f"(c[1]), "+f"(c[2]), "+f"(c[3])
        : "r"(a[0]), "r"(a[1]), "r"(a[2]), "r"(a[3]), "r"(b0), "r"(b1));
}
__device__ __forceinline__ uint32_t pack_h16(float x, float y) {
    __half2 t = __floats2half2_rn(x, y);
    return *(uint32_t*)&t;
}

// ---------------- fp16 single-product GEMM -------------------------------------
static constexpr uint32_t HA_BYTES = 128 * 80;
static constexpr uint32_t HB_BYTES = 256 * 80;
static constexpr uint32_t HSTAGE = HA_BYTES + HB_BYTES;
static constexpr uint32_t HALF_SMEM = 4 * HSTAGE;   // 122880

template <bool RELU, bool HALFOUT>
__global__ __launch_bounds__(512, 1) void gemm_half(
    const __half* __restrict__ A, const __half* __restrict__ B,
    const float* __restrict__ bias, void* __restrict__ Cout, int Nd, int Kd) {
    extern __shared__ char smem[];
    const uint32_t sb = smem_u32(smem);
    const int tid = threadIdx.x;
    const int wid = tid >> 5, lane = tid & 31;
    const int wm = wid & 1, wn = wid >> 1;
    const int bm = blockIdx.x * 128;
    const int bn = blockIdx.y * 256;
    const int NC = Kd >> 5;

    const int arow = tid >> 2, aseg = tid & 3;

    auto issue = [&](int c) {
        const int k0 = c << 5;
        const uint32_t base = sb + (c & 3) * HSTAGE;
        cp16(base + arow * 80 + aseg * 16, A + (size_t)(bm + arow) * Kd + k0 + aseg * 8);
#pragma unroll
        for (int it = 0; it < 2; it++) {
            int i = tid + it * 512;
            int br = i >> 2, bs = i & 3;
            cp16(base + HA_BYTES + br * 80 + bs * 16,
                 B + (size_t)(bn + br) * Kd + k0 + bs * 8);
        }
    };

    issue(0); cp_commit();
    issue(1); cp_commit();
    issue(2); cp_commit();

    float acc[4][4][4];
#pragma unroll
    for (int i = 0; i < 4; i++)
#pragma unroll
        for (int j = 0; j < 4; j++)
#pragma unroll
            for (int r = 0; r < 4; r++) acc[i][j][r] = 0.f;

    const int a_r = lane & 15;
    const int a_c = (lane >> 4) << 3;
    const int b_r = (lane & 7) + ((lane >> 4) << 3);
    const int b_c = ((lane >> 3) & 1) << 3;

    for (int c = 0; c < NC; c++) {
        cp_wait<2>();
        __syncthreads();
        if (c + 3 < NC) issue(c + 3);
        cp_commit();

        const uint32_t sA = sb + (c & 3) * HSTAGE;
        const uint32_t sB = sA + HA_BYTES;
#pragma unroll
        for (int kk = 0; kk < 2; kk++) {
            uint32_t a[4][4], b[2][4];
#pragma unroll
            for (int mt = 0; mt < 4; mt++)
                ldmat4(a[mt], sA + (uint32_t)(wm * 64 + mt * 16 + a_r) * 80
                              + (uint32_t)(kk * 16 + a_c) * 2);
#pragma unroll
            for (int g = 0; g < 2; g++)
                ldmat4(b[g], sB + (uint32_t)(wn * 32 + g * 16 + b_r) * 80
                             + (uint32_t)(kk * 16 + b_c) * 2);
#pragma unroll
            for (int mt = 0; mt < 4; mt++)
#pragma unroll
                for (int nt = 0; nt < 4; nt++)
                    mma16816h(acc[mt][nt], a[mt],
                              b[nt >> 1][(nt & 1) * 2], b[nt >> 1][(nt & 1) * 2 + 1]);
        }
    }

    const int g = lane >> 2, t = lane & 3;
#pragma unroll
    for (int mt = 0; mt < 4; mt++) {
#pragma unroll
        for (int nt = 0; nt < 4; nt++) {
            int row0 = bm + wm * 64 + mt * 16 + g;
            int col = bn + wn * 32 + nt * 8 + t * 2;
            float bx = bias[col], by = bias[col + 1];
            float2 v0, v1;
            v0.x = acc[mt][nt][0] + bx; v0.y = acc[mt][nt][1] + by;
            v1.x = acc[mt][nt][2] + bx; v1.y = acc[mt][nt][3] + by;
            if (RELU) {
                v0.x = fmaxf(v0.x, 0.f); v0.y = fmaxf(v0.y, 0.f);
                v1.x = fmaxf(v1.x, 0.f); v1.y = fmaxf(v1.y, 0.f);
            }
            if (HALFOUT) {
                __half* C = (__half*)Cout;
                *(__half2*)&C[(size_t)row0 * Nd + col] = __floats2half2_rn(v0.x, v0.y);
                *(__half2*)&C[(size_t)(row0 + 8) * Nd + col] = __floats2half2_rn(v1.x, v1.y);
            } else {
                float* C = (float*)Cout;
                *(float2*)&C[(size_t)row0 * Nd + col] = v0;
                *(float2*)&C[(size_t)(row0 + 8) * Nd + col] = v1;
            }
        }
    }
}

// ---------------- vectorized transpose to fp16: W[K,N] -> [N,K] ---------------
// float4 global loads into registers, scalar smem stores (33-stride stays
// conflict-free; 16B-alignment issue of float4 STS avoided).
__global__ __launch_bounds__(512) void thalf_kernel(
    const float* __restrict__ W, __half* __restrict__ out, int K, int N) {
    __shared__ float s[64][33];
    const int n0 = blockIdx.x * 32, k0 = blockIdx.y * 64;
    const int lin = threadIdx.y * 32 + threadIdx.x;    // blockDim (32,16)
    {
        int row = lin >> 3, col4 = (lin & 7) * 4;
        float4 v = *(const float4*)&W[(size_t)(k0 + row) * N + n0 + col4];
        s[row][col4 + 0] = v.x;
        s[row][col4 + 1] = v.y;
        s[row][col4 + 2] = v.z;
        s[row][col4 + 3] = v.w;
    }
    __syncthreads();
    const int tx = threadIdx.x;
#pragma unroll
    for (int wy = 0; wy < 2; wy++) {
        int nn = threadIdx.y + wy * 16;
        __half2 hv = __floats2half2_rn(s[tx * 2][nn], s[tx * 2 + 1][nn]);
        *(__half2*)&out[(size_t)(n0 + nn) * K + k0 + tx * 2] = hv;
    }
}

// ---------------- embed + positional encoding -> fp16 --------------------------
__global__ void embed_kernel(const int* __restrict__ x, const float* __restrict__ emb,
                             __half* __restrict__ h16) {
    int row = blockIdx.x;
    int t = row & (cfg::T - 1);
    int tok = x[row];
    const float* e = emb + (size_t)tok * cfg::D;
    int d0 = threadIdx.x * 4;
    float4 ev = *(const float4*)&e[d0];
    const float cfac = -0.017988946039015984f;
    int i0 = d0 >> 1;
    float f0 = expf((float)i0 * cfac);
    float f1 = expf((float)(i0 + 1) * cfac);
    float a0 = (float)t * f0, a1 = (float)t * f1;
    __half2 p0 = __floats2half2_rn(ev.x + sinf(a0), ev.y + cosf(a0));
    __half2 p1 = __floats2half2_rn(ev.z + sinf(a1), ev.w + cosf(a1));
    uint2 pk = make_uint2(*(uint32_t*)&p0, *(uint32_t*)&p1);
    *(uint2*)&h16[(size_t)row * cfg::D + d0] = pk;
}

// ---------------- fp16 flash attention (causal, double-buffered K/V) ----------
static constexpr int FH = 72;   // half stride (144B, multiple of 16)

__global__ __launch_bounds__(128) void flash_half(
    const __half* __restrict__ q, const __half* __restrict__ k,
    const __half* __restrict__ v, __half* __restrict__ o16) {
    __shared__ __align__(16) __half sQ[64 * FH];
    __shared__ __align__(16) __half sK[2][64 * FH];
    __shared__ __align__(16) __half sV[2][64 * FH];

    const int qi = gridDim.x - 1 - blockIdx.x;
    const int h = blockIdx.y, b = blockIdx.z;
    const int tid = threadIdx.x;
    const int wid = tid >> 5, lane = tid & 31;
    const size_t headoff = ((size_t)b * cfg::T) * cfg::D + (size_t)h * cfg::HD;

    const uint32_t uQ = smem_u32(sQ);
    const uint32_t uK0 = smem_u32(sK[0]), uV0 = smem_u32(sV[0]);

    const int a_r = lane & 15;
    const int a_c = (lane >> 4) << 3;
    const int b_r = (lane & 7) + ((lane >> 4) << 3);
    const int b_c = ((lane >> 3) & 1) << 3;
    const int kv_r = (lane & 7) + (((lane >> 3) & 1) << 3);   // trans: k-row within 16
    const int kv_c = (lane >> 4) << 3;                        // trans: n-col half
    const int g = lane >> 2, t = lane & 3;

    // Q tile via cp.async
#pragma unroll
    for (int it = 0; it < 4; it++) {
        int idx = tid + it * 128;
        int r = idx >> 3, seg = idx & 7;
        cp16(uQ + r * (FH * 2) + seg * 16,
             q + headoff + (size_t)(qi * 64 + r) * cfg::D + seg * 8);
    }
    cp_commit();

    auto issue_kv = [&](int kt) {
        const int buf = kt & 1;
        const uint32_t uk = uK0 + buf * (64 * FH * 2);
        const uint32_t uv = uV0 + buf * (64 * FH * 2);
#pragma unroll
        for (int it = 0; it < 4; it++) {
            int idx = tid + it * 128;
            int r = idx >> 3, seg = idx & 7;
            size_t go = headoff + (size_t)(kt * 64 + r) * cfg::D + seg * 8;
            cp16(uk + r * (FH * 2) + seg * 16, k + go);
            cp16(uv + r * (FH * 2) + seg * 16, v + go);
        }
    };

    issue_kv(0); cp_commit();

    float accO[8][4];
#pragma unroll
    for (int i = 0; i < 8; i++)
#pragma unroll
        for (int j = 0; j < 4; j++) accO[i][j] = 0.f;
    float m0 = -1e30f, m1 = -1e30f, l0 = 0.f, l1 = 0.f;

    for (int kt = 0; kt <= qi; kt++) {
        cp_wait<0>();
        __syncthreads();
        if (kt < qi) { issue_kv(kt + 1); cp_commit(); }

        const int buf = kt & 1;
        const uint32_t uk = uK0 + buf * (64 * FH * 2);
        const uint32_t uv = uV0 + buf * (64 * FH * 2);

        // S = Q @ K^T (fp16)
        float sa[8][4];
#pragma unroll
        for (int i = 0; i < 8; i++)
#pragma unroll
            for (int j = 0; j < 4; j++) sa[i][j] = 0.f;
#pragma unroll
        for (int kg = 0; kg < 4; kg++) {
            uint32_t af[4];
            ldmat4(af, uQ + (uint32_t)(wid * 16 + a_r) * (FH * 2) + (kg * 16 + a_c) * 2);
#pragma unroll
            for (int gg = 0; gg < 4; gg++) {
                uint32_t bf[4];
                ldmat4(bf, uk + (uint32_t)(gg * 16 + b_r) * (FH * 2) + (kg * 16 + b_c) * 2);
                mma16816h(sa[gg * 2], af, bf[0], bf[1]);
                mma16816h(sa[gg * 2 + 1], af, bf[2], bf[3]);
            }
        }

        // scale + causal mask
        const bool diag = (kt == qi);
#pragma unroll
        for (int nt = 0; nt < 8; nt++) {
            int c0 = nt * 8 + t * 2;
            sa[nt][0] *= 0.125f; sa[nt][1] *= 0.125f;
            sa[nt][2] *= 0.125f; sa[nt][3] *= 0.125f;
            if (diag) {
                int r0 = wid * 16 + g, r1 = r0 + 8;
                if (c0 > r0)     sa[nt][0] = -1e30f;
                if (c0 + 1 > r0) sa[nt][1] = -1e30f;
                if (c0 > r1)     sa[nt][2] = -1e30f;
                if (c0 + 1 > r1) sa[nt][3] = -1e30f;
            }
        }

        // online softmax (quad butterfly across the 4 lanes sharing a row)
        float mt0 = -1e30f, mt1 = -1e30f;
#pragma unroll
        for (int nt = 0; nt < 8; nt++) {
            mt0 = fmaxf(mt0, fmaxf(sa[nt][0], sa[nt][1]));
            mt1 = fmaxf(mt1, fmaxf(sa[nt][2], sa[nt][3]));
        }
#pragma unroll
        for (int off = 1; off <= 2; off <<= 1) {
            mt0 = fmaxf(mt0, __shfl_xor_sync(0xffffffffu, mt0, off));
            mt1 = fmaxf(mt1, __shfl_xor_sync(0xffffffffu, mt1, off));
        }
        float mn0 = fmaxf(m0, mt0), mn1 = fmaxf(m1, mt1);
        float al0 = __expf(m0 - mn0), al1 = __expf(m1 - mn1);
        m0 = mn0; m1 = mn1;

        float rs0 = 0.f, rs1 = 0.f;
#pragma unroll
        for (int nt = 0; nt < 8; nt++) {
            sa[nt][0] = __expf(sa[nt][0] - mn0);
            sa[nt][1] = __expf(sa[nt][1] - mn0);
            sa[nt][2] = __expf(sa[nt][2] - mn1);
            sa[nt][3] = __expf(sa[nt][3] - mn1);
            rs0 += sa[nt][0] + sa[nt][1];
            rs1 += sa[nt][2] + sa[nt][3];
        }
#pragma unroll
        for (int off = 1; off <= 2; off <<= 1) {
            rs0 += __shfl_xor_sync(0xffffffffu, rs0, off);
            rs1 += __shfl_xor_sync(0xffffffffu, rs1, off);
        }
        l0 = l0 * al0 + rs0;
        l1 = l1 * al1 + rs1;
#pragma unroll
        for (int nt = 0; nt < 8; nt++) {
            accO[nt][0] *= al0; accO[nt][1] *= al0;
            accO[nt][2] *= al1; accO[nt][3] *= al1;
        }

        // P fragments (fp16) straight from accumulators
        uint32_t pf[4][4];
#pragma unroll
        for (int kg = 0; kg < 4; kg++) {
            pf[kg][0] = pack_h16(sa[2 * kg][0],     sa[2 * kg][1]);
            pf[kg][1] = pack_h16(sa[2 * kg][2],     sa[2 * kg][3]);
            pf[kg][2] = pack_h16(sa[2 * kg + 1][0], sa[2 * kg + 1][1]);
            pf[kg][3] = pack_h16(sa[2 * kg + 1][2], sa[2 * kg + 1][3]);
        }

        // O += P @ V  (V natural [j][d]; trans ldmatrix for B fragments)
#pragma unroll
        for (int kg = 0; kg < 4; kg++) {
#pragma unroll
            for (int gg = 0; gg < 4; gg++) {
                uint32_t bf[4];
                ldmat4t(bf, uv + (uint32_t)(kg * 16 + kv_r) * (FH * 2) + (gg * 16 + kv_c) * 2);
                mma16816h(accO[gg * 2], pf[kg], bf[0], bf[1]);
                mma16816h(accO[gg * 2 + 1], pf[kg], bf[2], bf[3]);
            }
        }
    }

    float inv0 = 1.0f / l0, inv1 = 1.0f / l1;
    int row0 = qi * 64 + wid * 16 + g;
#pragma unroll
    for (int nt = 0; nt < 8; nt++) {
        int col = nt * 8 + t * 2;
        *(__half2*)&o16[headoff + (size_t)row0 * cfg::D + col] =
            __floats2half2_rn(accO[nt][0] * inv0, accO[nt][1] * inv0);
        *(__half2*)&o16[headoff + (size_t)(row0 + 8) * cfg::D + col] =
            __floats2half2_rn(accO[nt][2] * inv1, accO[nt][3] * inv1);
    }
}

// ---------------- layernorm (unbiased std), fp32 in -> fp16 out ----------------
__inline__ __device__ float block_reduce_sum(float val) {
    __shared__ float sbuf[8];
    int lane = threadIdx.x & 31, wid = threadIdx.x >> 5;
#pragma unroll
    for (int o = 16; o; o >>= 1) val += __shfl_xor_sync(0xffffffffu, val, o);
    if (lane == 0) sbuf[wid] = val;
    __syncthreads();
    val = (threadIdx.x < 8) ? sbuf[threadIdx.x] : 0.f;
    if (wid == 0) {
#pragma unroll
        for (int o = 4; o; o >>= 1) val += __shfl_xor_sync(0xffffffffu, val, o);
        if (lane == 0) sbuf[0] = val;
    }
    __syncthreads();
    float r = sbuf[0];
    __syncthreads();
    return r;
}

__global__ void layernorm_kernel(const float* __restrict__ in, __half* __restrict__ out16,
                                 const float* __restrict__ g, const float* __restrict__ be) {
    int row = blockIdx.x;
    const float* p = in + (size_t)row * cfg::D;
    int d0 = threadIdx.x * 4;
    float4 xv = *(const float4*)&p[d0];
    float s = xv.x + xv.y + xv.z + xv.w;
    s = block_reduce_sum(s);
    float mean = s * (1.0f / cfg::D);
    float dx[4] = {xv.x - mean, xv.y - mean, xv.z - mean, xv.w - mean};
    float sq = dx[0] * dx[0] + dx[1] * dx[1] + dx[2] * dx[2] + dx[3] * dx[3];
    sq = block_reduce_sum(sq);
    float stdv = sqrtf(sq / (float)(cfg::D - 1));
    float inv = 1.0f / (stdv + cfg::EPS);
    float4 gg = *(const float4*)&g[d0];
    float4 bb = *(const float4*)&be[d0];
    __half2 p0 = __floats2half2_rn(dx[0] * inv * gg.x + bb.x, dx[1] * inv * gg.y + bb.y);
    __half2 p1 = __floats2half2_rn(dx[2] * inv * gg.z + bb.z, dx[3] * inv * gg.w + bb.w);
    uint2 pk = make_uint2(*(uint32_t*)&p0, *(uint32_t*)&p1);
    *(uint2*)&out16[(size_t)row * cfg::D + d0] = pk;
}

// ---------------- row softmax over V=32000 -------------------------------------
__global__ void softmax_kernel(float* __restrict__ out) {
    int row = blockIdx.x;
    float* p = out + (size_t)row * cfg::V;
    float m = -1e30f, s = 0.f;
    for (int j = threadIdx.x; j < cfg::V; j += 256) {
        float xv = p[j];
        if (xv > m) { s = s * __expf(m - xv) + 1.0f; m = xv; }
        else        { s += __expf(xv - m); }
    }
    __shared__ float sm[256], ss[256];
    sm[threadIdx.x] = m; ss[threadIdx.x] = s;
    __syncthreads();
    for (int off = 128; off; off >>= 1) {
        if (threadIdx.x < off) {
            float m1 = sm[threadIdx.x], s1 = ss[threadIdx.x];
            float m2 = sm[threadIdx.x + off], s2 = ss[threadIdx.x + off];
            float mm = fmaxf(m1, m2);
            sm[threadIdx.x] = mm;
            ss[threadIdx.x] = s1 * __expf(m1 - mm) + s2 * __expf(m2 - mm);
        }
        __syncthreads();
    }
    float mall = sm[0];
    float inv = 1.0f / ss[0];
    for (int j = threadIdx.x; j < cfg::V; j += 256) {
        p[j] = __expf(p[j] - mall) * inv;
    }
}

// ---------------- host orchestration -------------------------------------------
extern "C" void kernel_launch(void* const* d_in, const int* in_sizes, int n_in,
                              void* d_out, int out_size) {
    using namespace cfg;
    const int*   x   = (const int*)d_in[0];
    const float* emb = (const float*)d_in[1];
    const float* Wq  = (const float*)d_in[2];
    const float* bq  = (const float*)d_in[3];
    const float* Wk  = (const float*)d_in[4];
    const float* bk  = (const float*)d_in[5];
    const float* Wv  = (const float*)d_in[6];
    const float* bv  = (const float*)d_in[7];
    const float* Wo  = (const float*)d_in[8];
    const float* bo  = (const float*)d_in[9];
    const float* g1  = (const float*)d_in[10];
    const float* be1 = (const float*)d_in[11];
    const float* W1  = (const float*)d_in[12];
    const float* bf1 = (const float*)d_in[13];
    const float* W2  = (const float*)d_in[14];
    const float* bf2 = (const float*)d_in[15];
    const float* g2  = (const float*)d_in[16];
    const float* be2 = (const float*)d_in[17];
    const float* Wl  = (const float*)d_in[18];
    const float* bl  = (const float*)d_in[19];
    float* out = (float*)d_out;

    float *h, *o;
    cudaGetSymbolAddress((void**)&h, g_h);
    cudaGetSymbolAddress((void**)&o, g_o);

    __half *x16, *h16, *o16, *q16, *k16, *v16, *wq, *wk, *wv, *wo, *w1, *w2, *wl;
    cudaGetSymbolAddress((void**)&x16, g_x16);
    cudaGetSymbolAddress((void**)&h16, g_h16);
    cudaGetSymbolAddress((void**)&o16, g_o16);
    cudaGetSymbolAddress((void**)&q16, g_q16);
    cudaGetSymbolAddress((void**)&k16, g_k16);
    cudaGetSymbolAddress((void**)&v16, g_v16);
    cudaGetSymbolAddress((void**)&wq, g_wq);
    cudaGetSymbolAddress((void**)&wk, g_wk);
    cudaGetSymbolAddress((void**)&wv, g_wv);
    cudaGetSymbolAddress((void**)&wo, g_wo);
    cudaGetSymbolAddress((void**)&w1, g_w1);
    cudaGetSymbolAddress((void**)&w2, g_w2);
    cudaGetSymbolAddress((void**)&wl, g_wl);

    cudaFuncSetAttribute((const void*)gemm_half<false, false>,
                         cudaFuncAttributeMaxDynamicSharedMemorySize, HALF_SMEM);
    cudaFuncSetAttribute((const void*)gemm_half<true, true>,
                         cudaFuncAttributeMaxDynamicSharedMemorySize, HALF_SMEM);
    cudaFuncSetAttribute((const void*)gemm_half<false, true>,
                         cudaFuncAttributeMaxDynamicSharedMemorySize, HALF_SMEM);

    dim3 tb(32, 16);
    embed_kernel<<<M, 256>>>(x, emb, h16);                                // 0
    thalf_kernel<<<dim3(D / 32, D / 64), tb>>>(Wq, wq, D, D);             // 1
    thalf_kernel<<<dim3(D / 32, D / 64), tb>>>(Wk, wk, D, D);             // 2
    thalf_kernel<<<dim3(D / 32, D / 64), tb>>>(Wv, wv, D, D);             // 3
    thalf_kernel<<<dim3(D / 32, D / 64), tb>>>(Wo, wo, D, D);             // 4
    gemm_half<false, true><<<dim3(M / 128, D / 256), 512, HALF_SMEM>>>(   // 5 (ncu)
        h16, wq, bq, q16, D, D);
    gemm_half<false, true><<<dim3(M / 128, D / 256), 512, HALF_SMEM>>>(h16, wk, bk, k16, D, D);
    gemm_half<false, true><<<dim3(M / 128, D / 256), 512, HALF_SMEM>>>(h16, wv, bv, v16, D, D);

    flash_half<<<dim3(T / 64, H, B), 128>>>(q16, k16, v16, o16);

    gemm_half<false, false><<<dim3(M / 128, D / 256), 512, HALF_SMEM>>>(o16, wo, bo, h, D, D);
    layernorm_kernel<<<M, 256>>>(h, h16, g1, be1);

    thalf_kernel<<<dim3(F / 32, D / 64), tb>>>(W1, w1, D, F);
    gemm_half<true, true><<<dim3(M / 128, F / 256), 512, HALF_SMEM>>>(h16, w1, bf1, x16, F, D);

    thalf_kernel<<<dim3(D / 32, F / 64), tb>>>(W2, w2, F, D);
    gemm_half<false, false><<<dim3(M / 128, D / 256), 512, HALF_SMEM>>>(x16, w2, bf2, o, D, F);
    layernorm_kernel<<<M, 256>>>(o, o16, g2, be2);

    thalf_kernel<<<dim3(V / 32, D / 64), tb>>>(Wl, wl, D, V);
    gemm_half<false, false><<<dim3(M / 128, V / 256), 512, HALF_SMEM>>>(o16, wl, bl, out, V, D);

    softmax_kernel<<<M, 256>>>(out);
}

// round 11
// speedup vs baseline: 5.3048x; 1.0384x over previous
#include <cuda_runtime.h>
#include <cuda_fp16.h>
#include <math.h>
#include <stdint.h>

// ---------------- problem constants ----------------
namespace cfg {
constexpr int B = 2, T = 2048, D = 1024, H = 16, HD = 64, F = 4096, V = 32000;
constexpr int M = B * T;
constexpr float EPS = 1e-6f;
}

// ---------------- scratch ----------------------------------------------------
__device__ float g_h[cfg::M * cfg::D];     // fp32 staging (Wo out)
__device__ float g_o[cfg::M * cfg::D];     // fp32 staging (FFN2 out)

__device__ __half g_x16[(size_t)cfg::M * cfg::F];   // FFN1 out
__device__ __half g_h16[cfg::M * cfg::D];           // embed out / LN1 out
__device__ __half g_o16[cfg::M * cfg::D];           // flash out / LN2 out
__device__ __half g_q16[cfg::M * cfg::D];
__device__ __half g_k16[cfg::M * cfg::D];
__device__ __half g_v16[cfg::M * cfg::D];

// fp16 weights in NATURAL [K,N] layout (straight conversion, no transpose)
__device__ __half g_wq[cfg::D * cfg::D], g_wk[cfg::D * cfg::D];
__device__ __half g_wv[cfg::D * cfg::D], g_wo[cfg::D * cfg::D];
__device__ __half g_w1[(size_t)cfg::D * cfg::F], g_w2[(size_t)cfg::D * cfg::F];
__device__ __half g_wl[(size_t)cfg::V * cfg::D];

// ---------------- PTX helpers -------------------------------------------------
__device__ __forceinline__ uint32_t smem_u32(const void* p) {
    uint32_t a;
    asm("{ .reg .u64 t; cvta.to.shared.u64 t, %1; cvt.u32.u64 %0, t; }" : "=r"(a) : "l"(p));
    return a;
}
__device__ __forceinline__ void cp16(uint32_t dst, const void* src) {
    asm volatile("cp.async.cg.shared.global [%0], [%1], 16;" :: "r"(dst), "l"(src));
}
__device__ __forceinline__ void cp_commit() {
    asm volatile("cp.async.commit_group;" ::: "memory");
}
template <int N>
__device__ __forceinline__ void cp_wait() {
    asm volatile("cp.async.wait_group %0;" :: "n"(N) : "memory");
}
__device__ __forceinline__ void ldmat4(uint32_t* r, uint32_t addr) {
    asm volatile("ldmatrix.sync.aligned.m8n8.x4.shared.b16 {%0,%1,%2,%3}, [%4];"
                 : "=r"(r[0]), "=r"(r[1]), "=r"(r[2]), "=r"(r[3]) : "r"(addr));
}
__device__ __forceinline__ void ldmat4t(uint32_t* r, uint32_t addr) {
    asm volatile("ldmatrix.sync.aligned.m8n8.x4.trans.shared.b16 {%0,%1,%2,%3}, [%4];"
                 : "=r"(r[0]), "=r"(r[1]), "=r"(r[2]), "=r"(r[3]) : "r"(addr));
}
__device__ __forceinline__ void mma16816h(float* c, const uint32_t* a, uint32_t b0, uint32_t b1) {
    asm volatile(
        "mma.sync.aligned.m16n8k16.row.col.f32.f16.f16.f32 "
        "{%0,%1,%2,%3}, {%4,%5,%6,%7}, {%8,%9}, {%0,%1,%2,%3};"
        : "+f"(c[0]), "+f"(c[1]), "+f"(c[2]), "+f"(c[3])
        : "r"(a[0]), "r"(a[1]), "r"(a[2]), "r"(a[3]), "r"(b0), "r"(b1));
}
__device__ __forceinline__ uint32_t pack_h16(float x, float y) {
    __half2 t = __floats2half2_rn(x, y);
    return *(uint32_t*)&t;
}

// ---------------- fp16 GEMM, B in natural [K,N] layout (trans-ldmatrix) --------
// C[M,N] = A[M,K] @ B[K,N] + bias. CTA 128x256, BK=32, 512 thr (16 warps 2x8),
// 4-stage cp.async. A stride 80B; B tile 32(k) x 256(n), stride 528B.
static constexpr uint32_t TA_BYTES = 128 * 80;               // 10240
static constexpr int BSTR = 264;                             // halves (528B)
static constexpr uint32_t TB_BYTES = 32 * BSTR * 2;          // 16896
static constexpr uint32_t TSTAGE = TA_BYTES + TB_BYTES;      // 27136
static constexpr uint32_t TN_SMEM = 4 * TSTAGE;              // 108544

template <bool RELU, bool HALFOUT>
__global__ __launch_bounds__(512, 1) void gemm_tn(
    const __half* __restrict__ A, const __half* __restrict__ B,
    const float* __restrict__ bias, void* __restrict__ Cout, int Nd, int Kd) {
    extern __shared__ char smem[];
    const uint32_t sb = smem_u32(smem);
    const int tid = threadIdx.x;
    const int wid = tid >> 5, lane = tid & 31;
    const int wm = wid & 1, wn = wid >> 1;
    const int bm = blockIdx.x * 128;
    const int bn = blockIdx.y * 256;
    const int NC = Kd >> 5;

    const int arow = tid >> 2, aseg = tid & 3;

    auto issue = [&](int c) {
        const int k0 = c << 5;
        const uint32_t base = sb + (c & 3) * TSTAGE;
        cp16(base + arow * 80 + aseg * 16, A + (size_t)(bm + arow) * Kd + k0 + aseg * 8);
#pragma unroll
        for (int it = 0; it < 2; it++) {
            int i = tid + it * 512;
            int row = i >> 5, seg = i & 31;          // 32 k-rows x 32 segs(16B)
            cp16(base + TA_BYTES + row * (BSTR * 2) + seg * 16,
                 B + (size_t)(k0 + row) * Nd + bn + seg * 8);
        }
    };

    issue(0); cp_commit();
    issue(1); cp_commit();
    issue(2); cp_commit();

    float acc[4][4][4];
#pragma unroll
    for (int i = 0; i < 4; i++)
#pragma unroll
        for (int j = 0; j < 4; j++)
#pragma unroll
            for (int r = 0; r < 4; r++) acc[i][j][r] = 0.f;

    const int a_r = lane & 15;
    const int a_c = (lane >> 4) << 3;
    const int tr_r = (lane & 7) + (((lane >> 3) & 1) << 3);  // k-row within 16
    const int tr_c = (lane >> 4) << 3;                       // n-col half

    for (int c = 0; c < NC; c++) {
        cp_wait<2>();
        __syncthreads();
        if (c + 3 < NC) issue(c + 3);
        cp_commit();

        const uint32_t sA = sb + (c & 3) * TSTAGE;
        const uint32_t sB = sA + TA_BYTES;
#pragma unroll
        for (int kk = 0; kk < 2; kk++) {
            uint32_t a[4][4], b[2][4];
#pragma unroll
            for (int mt = 0; mt < 4; mt++)
                ldmat4(a[mt], sA + (uint32_t)(wm * 64 + mt * 16 + a_r) * 80
                              + (uint32_t)(kk * 16 + a_c) * 2);
#pragma unroll
            for (int g = 0; g < 2; g++)
                ldmat4t(b[g], sB + (uint32_t)(kk * 16 + tr_r) * (BSTR * 2)
                              + (uint32_t)(wn * 32 + g * 16 + tr_c) * 2);
#pragma unroll
            for (int mt = 0; mt < 4; mt++)
#pragma unroll
                for (int nt = 0; nt < 4; nt++)
                    mma16816h(acc[mt][nt], a[mt],
                              b[nt >> 1][(nt & 1) * 2], b[nt >> 1][(nt & 1) * 2 + 1]);
        }
    }

    const int g = lane >> 2, t = lane & 3;
#pragma unroll
    for (int mt = 0; mt < 4; mt++) {
#pragma unroll
        for (int nt = 0; nt < 4; nt++) {
            int row0 = bm + wm * 64 + mt * 16 + g;
            int col = bn + wn * 32 + nt * 8 + t * 2;
            float bx = bias[col], by = bias[col + 1];
            float2 v0, v1;
            v0.x = acc[mt][nt][0] + bx; v0.y = acc[mt][nt][1] + by;
            v1.x = acc[mt][nt][2] + bx; v1.y = acc[mt][nt][3] + by;
            if (RELU) {
                v0.x = fmaxf(v0.x, 0.f); v0.y = fmaxf(v0.y, 0.f);
                v1.x = fmaxf(v1.x, 0.f); v1.y = fmaxf(v1.y, 0.f);
            }
            if (HALFOUT) {
                __half* C = (__half*)Cout;
                *(__half2*)&C[(size_t)row0 * Nd + col] = __floats2half2_rn(v0.x, v0.y);
                *(__half2*)&C[(size_t)(row0 + 8) * Nd + col] = __floats2half2_rn(v1.x, v1.y);
            } else {
                float* C = (float*)Cout;
                *(float2*)&C[(size_t)row0 * Nd + col] = v0;
                *(float2*)&C[(size_t)(row0 + 8) * Nd + col] = v1;
            }
        }
    }
}

// ---------------- weight convert fp32 -> fp16 (same layout, coalesced) ---------
__global__ void wconv_kernel(const float* __restrict__ W, __half* __restrict__ out,
                             int n4) {
    int i = blockIdx.x * 256 + threadIdx.x;
    if (i >= n4) return;
    float4 v = ((const float4*)W)[i];
    ((__half2*)out)[i * 2 + 0] = __floats2half2_rn(v.x, v.y);
    ((__half2*)out)[i * 2 + 1] = __floats2half2_rn(v.z, v.w);
}

// ---------------- embed + positional encoding -> fp16 --------------------------
__global__ void embed_kernel(const int* __restrict__ x, const float* __restrict__ emb,
                             __half* __restrict__ h16) {
    int row = blockIdx.x;
    int t = row & (cfg::T - 1);
    int tok = x[row];
    const float* e = emb + (size_t)tok * cfg::D;
    int d0 = threadIdx.x * 4;
    float4 ev = *(const float4*)&e[d0];
    const float cfac = -0.017988946039015984f;
    int i0 = d0 >> 1;
    float f0 = expf((float)i0 * cfac);
    float f1 = expf((float)(i0 + 1) * cfac);
    float a0 = (float)t * f0, a1 = (float)t * f1;
    __half2 p0 = __floats2half2_rn(ev.x + sinf(a0), ev.y + cosf(a0));
    __half2 p1 = __floats2half2_rn(ev.z + sinf(a1), ev.w + cosf(a1));
    uint2 pk = make_uint2(*(uint32_t*)&p0, *(uint32_t*)&p1);
    *(uint2*)&h16[(size_t)row * cfg::D + d0] = pk;
}

// ---------------- fp16 flash attention (causal, double-buffered K/V) ----------
static constexpr int FH = 72;

__global__ __launch_bounds__(128) void flash_half(
    const __half* __restrict__ q, const __half* __restrict__ k,
    const __half* __restrict__ v, __half* __restrict__ o16) {
    __shared__ __align__(16) __half sQ[64 * FH];
    __shared__ __align__(16) __half sK[2][64 * FH];
    __shared__ __align__(16) __half sV[2][64 * FH];

    const int qi = gridDim.x - 1 - blockIdx.x;
    const int h = blockIdx.y, b = blockIdx.z;
    const int tid = threadIdx.x;
    const int wid = tid >> 5, lane = tid & 31;
    const size_t headoff = ((size_t)b * cfg::T) * cfg::D + (size_t)h * cfg::HD;

    const uint32_t uQ = smem_u32(sQ);
    const uint32_t uK0 = smem_u32(sK[0]), uV0 = smem_u32(sV[0]);

    const int a_r = lane & 15;
    const int a_c = (lane >> 4) << 3;
    const int b_r = (lane & 7) + ((lane >> 4) << 3);
    const int b_c = ((lane >> 3) & 1) << 3;
    const int kv_r = (lane & 7) + (((lane >> 3) & 1) << 3);
    const int kv_c = (lane >> 4) << 3;
    const int g = lane >> 2, t = lane & 3;

#pragma unroll
    for (int it = 0; it < 4; it++) {
        int idx = tid + it * 128;
        int r = idx >> 3, seg = idx & 7;
        cp16(uQ + r * (FH * 2) + seg * 16,
             q + headoff + (size_t)(qi * 64 + r) * cfg::D + seg * 8);
    }
    cp_commit();

    auto issue_kv = [&](int kt) {
        const int buf = kt & 1;
        const uint32_t uk = uK0 + buf * (64 * FH * 2);
        const uint32_t uv = uV0 + buf * (64 * FH * 2);
#pragma unroll
        for (int it = 0; it < 4; it++) {
            int idx = tid + it * 128;
            int r = idx >> 3, seg = idx & 7;
            size_t go = headoff + (size_t)(kt * 64 + r) * cfg::D + seg * 8;
            cp16(uk + r * (FH * 2) + seg * 16, k + go);
            cp16(uv + r * (FH * 2) + seg * 16, v + go);
        }
    };

    issue_kv(0); cp_commit();

    float accO[8][4];
#pragma unroll
    for (int i = 0; i < 8; i++)
#pragma unroll
        for (int j = 0; j < 4; j++) accO[i][j] = 0.f;
    float m0 = -1e30f, m1 = -1e30f, l0 = 0.f, l1 = 0.f;

    for (int kt = 0; kt <= qi; kt++) {
        cp_wait<0>();
        __syncthreads();
        if (kt < qi) { issue_kv(kt + 1); cp_commit(); }

        const int buf = kt & 1;
        const uint32_t uk = uK0 + buf * (64 * FH * 2);
        const uint32_t uv = uV0 + buf * (64 * FH * 2);

        float sa[8][4];
#pragma unroll
        for (int i = 0; i < 8; i++)
#pragma unroll
            for (int j = 0; j < 4; j++) sa[i][j] = 0.f;
#pragma unroll
        for (int kg = 0; kg < 4; kg++) {
            uint32_t af[4];
            ldmat4(af, uQ + (uint32_t)(wid * 16 + a_r) * (FH * 2) + (kg * 16 + a_c) * 2);
#pragma unroll
            for (int gg = 0; gg < 4; gg++) {
                uint32_t bf[4];
                ldmat4(bf, uk + (uint32_t)(gg * 16 + b_r) * (FH * 2) + (kg * 16 + b_c) * 2);
                mma16816h(sa[gg * 2], af, bf[0], bf[1]);
                mma16816h(sa[gg * 2 + 1], af, bf[2], bf[3]);
            }
        }

        const bool diag = (kt == qi);
#pragma unroll
        for (int nt = 0; nt < 8; nt++) {
            int c0 = nt * 8 + t * 2;
            sa[nt][0] *= 0.125f; sa[nt][1] *= 0.125f;
            sa[nt][2] *= 0.125f; sa[nt][3] *= 0.125f;
            if (diag) {
                int r0 = wid * 16 + g, r1 = r0 + 8;
                if (c0 > r0)     sa[nt][0] = -1e30f;
                if (c0 + 1 > r0) sa[nt][1] = -1e30f;
                if (c0 > r1)     sa[nt][2] = -1e30f;
                if (c0 + 1 > r1) sa[nt][3] = -1e30f;
            }
        }

        float mt0 = -1e30f, mt1 = -1e30f;
#pragma unroll
        for (int nt = 0; nt < 8; nt++) {
            mt0 = fmaxf(mt0, fmaxf(sa[nt][0], sa[nt][1]));
            mt1 = fmaxf(mt1, fmaxf(sa[nt][2], sa[nt][3]));
        }
#pragma unroll
        for (int off = 1; off <= 2; off <<= 1) {
            mt0 = fmaxf(mt0, __shfl_xor_sync(0xffffffffu, mt0, off));
            mt1 = fmaxf(mt1, __shfl_xor_sync(0xffffffffu, mt1, off));
        }
        float mn0 = fmaxf(m0, mt0), mn1 = fmaxf(m1, mt1);
        float al0 = __expf(m0 - mn0), al1 = __expf(m1 - mn1);
        m0 = mn0; m1 = mn1;

        float rs0 = 0.f, rs1 = 0.f;
#pragma unroll
        for (int nt = 0; nt < 8; nt++) {
            sa[nt][0] = __expf(sa[nt][0] - mn0);
            sa[nt][1] = __expf(sa[nt][1] - mn0);
            sa[nt][2] = __expf(sa[nt][2] - mn1);
            sa[nt][3] = __expf(sa[nt][3] - mn1);
            rs0 += sa[nt][0] + sa[nt][1];
            rs1 += sa[nt][2] + sa[nt][3];
        }
#pragma unroll
        for (int off = 1; off <= 2; off <<= 1) {
            rs0 += __shfl_xor_sync(0xffffffffu, rs0, off);
            rs1 += __shfl_xor_sync(0xffffffffu, rs1, off);
        }
        l0 = l0 * al0 + rs0;
        l1 = l1 * al1 + rs1;
#pragma unroll
        for (int nt = 0; nt < 8; nt++) {
            accO[nt][0] *= al0; accO[nt][1] *= al0;
            accO[nt][2] *= al1; accO[nt][3] *= al1;
        }

        uint32_t pf[4][4];
#pragma unroll
        for (int kg = 0; kg < 4; kg++) {
            pf[kg][0] = pack_h16(sa[2 * kg][0],     sa[2 * kg][1]);
            pf[kg][1] = pack_h16(sa[2 * kg][2],     sa[2 * kg][3]);
            pf[kg][2] = pack_h16(sa[2 * kg + 1][0], sa[2 * kg + 1][1]);
            pf[kg][3] = pack_h16(sa[2 * kg + 1][2], sa[2 * kg + 1][3]);
        }

#pragma unroll
        for (int kg = 0; kg < 4; kg++) {
#pragma unroll
            for (int gg = 0; gg < 4; gg++) {
                uint32_t bf[4];
                ldmat4t(bf, uv + (uint32_t)(kg * 16 + kv_r) * (FH * 2) + (gg * 16 + kv_c) * 2);
                mma16816h(accO[gg * 2], pf[kg], bf[0], bf[1]);
                mma16816h(accO[gg * 2 + 1], pf[kg], bf[2], bf[3]);
            }
        }
    }

    float inv0 = 1.0f / l0, inv1 = 1.0f / l1;
    int row0 = qi * 64 + wid * 16 + g;
#pragma unroll
    for (int nt = 0; nt < 8; nt++) {
        int col = nt * 8 + t * 2;
        *(__half2*)&o16[headoff + (size_t)row0 * cfg::D + col] =
            __floats2half2_rn(accO[nt][0] * inv0, accO[nt][1] * inv0);
        *(__half2*)&o16[headoff + (size_t)(row0 + 8) * cfg::D + col] =
            __floats2half2_rn(accO[nt][2] * inv1, accO[nt][3] * inv1);
    }
}

// ---------------- layernorm (unbiased std), fp32 in -> fp16 out ----------------
__inline__ __device__ float block_reduce_sum(float val) {
    __shared__ float sbuf[8];
    int lane = threadIdx.x & 31, wid = threadIdx.x >> 5;
#pragma unroll
    for (int o = 16; o; o >>= 1) val += __shfl_xor_sync(0xffffffffu, val, o);
    if (lane == 0) sbuf[wid] = val;
    __syncthreads();
    val = (threadIdx.x < 8) ? sbuf[threadIdx.x] : 0.f;
    if (wid == 0) {
#pragma unroll
        for (int o = 4; o; o >>= 1) val += __shfl_xor_sync(0xffffffffu, val, o);
        if (lane == 0) sbuf[0] = val;
    }
    __syncthreads();
    float r = sbuf[0];
    __syncthreads();
    return r;
}

__global__ void layernorm_kernel(const float* __restrict__ in, __half* __restrict__ out16,
                                 const float* __restrict__ g, const float* __restrict__ be) {
    int row = blockIdx.x;
    const float* p = in + (size_t)row * cfg::D;
    int d0 = threadIdx.x * 4;
    float4 xv = *(const float4*)&p[d0];
    float s = xv.x + xv.y + xv.z + xv.w;
    s = block_reduce_sum(s);
    float mean = s * (1.0f / cfg::D);
    float dx[4] = {xv.x - mean, xv.y - mean, xv.z - mean, xv.w - mean};
    float sq = dx[0] * dx[0] + dx[1] * dx[1] + dx[2] * dx[2] + dx[3] * dx[3];
    sq = block_reduce_sum(sq);
    float stdv = sqrtf(sq / (float)(cfg::D - 1));
    float inv = 1.0f / (stdv + cfg::EPS);
    float4 gg = *(const float4*)&g[d0];
    float4 bb = *(const float4*)&be[d0];
    __half2 p0 = __floats2half2_rn(dx[0] * inv * gg.x + bb.x, dx[1] * inv * gg.y + bb.y);
    __half2 p1 = __floats2half2_rn(dx[2] * inv * gg.z + bb.z, dx[3] * inv * gg.w + bb.w);
    uint2 pk = make_uint2(*(uint32_t*)&p0, *(uint32_t*)&p1);
    *(uint2*)&out16[(size_t)row * cfg::D + d0] = pk;
}

// ---------------- row softmax over V=32000 -------------------------------------
__global__ void softmax_kernel(float* __restrict__ out) {
    int row = blockIdx.x;
    float* p = out + (size_t)row * cfg::V;
    float m = -1e30f, s = 0.f;
    for (int j = threadIdx.x; j < cfg::V; j += 256) {
        float xv = p[j];
        if (xv > m) { s = s * __expf(m - xv) + 1.0f; m = xv; }
        else        { s += __expf(xv - m); }
    }
    __shared__ float sm[256], ss[256];
    sm[threadIdx.x] = m; ss[threadIdx.x] = s;
    __syncthreads();
    for (int off = 128; off; off >>= 1) {
        if (threadIdx.x < off) {
            float m1 = sm[threadIdx.x], s1 = ss[threadIdx.x];
            float m2 = sm[threadIdx.x + off], s2 = ss[threadIdx.x + off];
            float mm = fmaxf(m1, m2);
            sm[threadIdx.x] = mm;
            ss[threadIdx.x] = s1 * __expf(m1 - mm) + s2 * __expf(m2 - mm);
        }
        __syncthreads();
    }
    float mall = sm[0];
    float inv = 1.0f / ss[0];
    for (int j = threadIdx.x; j < cfg::V; j += 256) {
        p[j] = __expf(p[j] - mall) * inv;
    }
}

// ---------------- host orchestration -------------------------------------------
extern "C" void kernel_launch(void* const* d_in, const int* in_sizes, int n_in,
                              void* d_out, int out_size) {
    using namespace cfg;
    const int*   x   = (const int*)d_in[0];
    const float* emb = (const float*)d_in[1];
    const float* Wq  = (const float*)d_in[2];
    const float* bq  = (const float*)d_in[3];
    const float* Wk  = (const float*)d_in[4];
    const float* bk  = (const float*)d_in[5];
    const float* Wv  = (const float*)d_in[6];
    const float* bv  = (const float*)d_in[7];
    const float* Wo  = (const float*)d_in[8];
    const float* bo  = (const float*)d_in[9];
    const float* g1  = (const float*)d_in[10];
    const float* be1 = (const float*)d_in[11];
    const float* W1  = (const float*)d_in[12];
    const float* bf1 = (const float*)d_in[13];
    const float* W2  = (const float*)d_in[14];
    const float* bf2 = (const float*)d_in[15];
    const float* g2  = (const float*)d_in[16];
    const float* be2 = (const float*)d_in[17];
    const float* Wl  = (const float*)d_in[18];
    const float* bl  = (const float*)d_in[19];
    float* out = (float*)d_out;

    float *h, *o;
    cudaGetSymbolAddress((void**)&h, g_h);
    cudaGetSymbolAddress((void**)&o, g_o);

    __half *x16, *h16, *o16, *q16, *k16, *v16, *wq, *wk, *wv, *wo, *w1, *w2, *wl;
    cudaGetSymbolAddress((void**)&x16, g_x16);
    cudaGetSymbolAddress((void**)&h16, g_h16);
    cudaGetSymbolAddress((void**)&o16, g_o16);
    cudaGetSymbolAddress((void**)&q16, g_q16);
    cudaGetSymbolAddress((void**)&k16, g_k16);
    cudaGetSymbolAddress((void**)&v16, g_v16);
    cudaGetSymbolAddress((void**)&wq, g_wq);
    cudaGetSymbolAddress((void**)&wk, g_wk);
    cudaGetSymbolAddress((void**)&wv, g_wv);
    cudaGetSymbolAddress((void**)&wo, g_wo);
    cudaGetSymbolAddress((void**)&w1, g_w1);
    cudaGetSymbolAddress((void**)&w2, g_w2);
    cudaGetSymbolAddress((void**)&wl, g_wl);

    cudaFuncSetAttribute((const void*)gemm_tn<false, false>,
                         cudaFuncAttributeMaxDynamicSharedMemorySize, TN_SMEM);
    cudaFuncSetAttribute((const void*)gemm_tn<true, true>,
                         cudaFuncAttributeMaxDynamicSharedMemorySize, TN_SMEM);
    cudaFuncSetAttribute((const void*)gemm_tn<false, true>,
                         cudaFuncAttributeMaxDynamicSharedMemorySize, TN_SMEM);

    embed_kernel<<<M, 256>>>(x, emb, h16);
    wconv_kernel<<<D * D / 1024, 256>>>(Wq, wq, D * D / 4);
    wconv_kernel<<<D * D / 1024, 256>>>(Wk, wk, D * D / 4);
    wconv_kernel<<<D * D / 1024, 256>>>(Wv, wv, D * D / 4);
    wconv_kernel<<<D * D / 1024, 256>>>(Wo, wo, D * D / 4);
    gemm_tn<false, true><<<dim3(M / 128, D / 256), 512, TN_SMEM>>>(h16, wq, bq, q16, D, D);
    gemm_tn<false, true><<<dim3(M / 128, D / 256), 512, TN_SMEM>>>(h16, wk, bk, k16, D, D);
    gemm_tn<false, true><<<dim3(M / 128, D / 256), 512, TN_SMEM>>>(h16, wv, bv, v16, D, D);

    flash_half<<<dim3(T / 64, H, B), 128>>>(q16, k16, v16, o16);

    gemm_tn<false, false><<<dim3(M / 128, D / 256), 512, TN_SMEM>>>(o16, wo, bo, h, D, D);
    layernorm_kernel<<<M, 256>>>(h, h16, g1, be1);

    wconv_kernel<<<D * F / 1024, 256>>>(W1, w1, D * F / 4);
    gemm_tn<true, true><<<dim3(M / 128, F / 256), 512, TN_SMEM>>>(h16, w1, bf1, x16, F, D);

    wconv_kernel<<<D * F / 1024, 256>>>(W2, w2, D * F / 4);
    gemm_tn<false, false><<<dim3(M / 128, D / 256), 512, TN_SMEM>>>(x16, w2, bf2, o, D, F);
    layernorm_kernel<<<M, 256>>>(o, o16, g2, be2);

    wconv_kernel<<<D * V / 1024, 256>>>(Wl, wl, D * V / 4);
    gemm_tn<false, false><<<dim3(M / 128, V / 256), 512, TN_SMEM>>>(o16, wl, bl, out, V, D);

    softmax_kernel<<<M, 256>>>(out);
}

// round 12
// speedup vs baseline: 5.3086x; 1.0007x over previous
#include <cuda_runtime.h>
#include <cuda_fp16.h>
#include <math.h>
#include <stdint.h>

// ---------------- problem constants ----------------
namespace cfg {
constexpr int B = 2, T = 2048, D = 1024, H = 16, HD = 64, F = 4096, V = 32000;
constexpr int M = B * T;
constexpr float EPS = 1e-6f;
}

// ---------------- scratch ----------------------------------------------------
__device__ float g_h[cfg::M * cfg::D];     // fp32 staging (Wo out)
__device__ float g_o[cfg::M * cfg::D];     // fp32 staging (FFN2 out)

__device__ __half g_x16[(size_t)cfg::M * cfg::F];   // FFN1 out
__device__ __half g_h16[cfg::M * cfg::D];           // embed out / LN1 out
__device__ __half g_o16[cfg::M * cfg::D];           // flash out / LN2 out
__device__ __half g_q16[cfg::M * cfg::D];
__device__ __half g_k16[cfg::M * cfg::D];
__device__ __half g_v16[cfg::M * cfg::D];

// fp16 weights in NATURAL [K,N] layout (straight conversion, no transpose)
__device__ __half g_wq[cfg::D * cfg::D], g_wk[cfg::D * cfg::D];
__device__ __half g_wv[cfg::D * cfg::D], g_wo[cfg::D * cfg::D];
__device__ __half g_w1[(size_t)cfg::D * cfg::F], g_w2[(size_t)cfg::D * cfg::F];
__device__ __half g_wl[(size_t)cfg::V * cfg::D];

// ---------------- PTX helpers -------------------------------------------------
__device__ __forceinline__ uint32_t smem_u32(const void* p) {
    uint32_t a;
    asm("{ .reg .u64 t; cvta.to.shared.u64 t, %1; cvt.u32.u64 %0, t; }" : "=r"(a) : "l"(p));
    return a;
}
__device__ __forceinline__ void cp16(uint32_t dst, const void* src) {
    asm volatile("cp.async.cg.shared.global [%0], [%1], 16;" :: "r"(dst), "l"(src));
}
__device__ __forceinline__ void cp_commit() {
    asm volatile("cp.async.commit_group;" ::: "memory");
}
template <int N>
__device__ __forceinline__ void cp_wait() {
    asm volatile("cp.async.wait_group %0;" :: "n"(N) : "memory");
}
__device__ __forceinline__ void ldmat4(uint32_t* r, uint32_t addr) {
    asm volatile("ldmatrix.sync.aligned.m8n8.x4.shared.b16 {%0,%1,%2,%3}, [%4];"
                 : "=r"(r[0]), "=r"(r[1]), "=r"(r[2]), "=r"(r[3]) : "r"(addr));
}
__device__ __forceinline__ void ldmat4t(uint32_t* r, uint32_t addr) {
    asm volatile("ldmatrix.sync.aligned.m8n8.x4.trans.shared.b16 {%0,%1,%2,%3}, [%4];"
                 : "=r"(r[0]), "=r"(r[1]), "=r"(r[2]), "=r"(r[3]) : "r"(addr));
}
__device__ __forceinline__ void mma16816h(float* c, const uint32_t* a, uint32_t b0, uint32_t b1) {
    asm volatile(
        "mma.sync.aligned.m16n8k16.row.col.f32.f16.f16.f32 "
        "{%0,%1,%2,%3}, {%4,%5,%6,%7}, {%8,%9}, {%0,%1,%2,%3};"
        : "+f"(c[0]), "+f"(c[1]), "+f"(c[2]), "+f"(c[3])
        : "r"(a[0]), "r"(a[1]), "r"(a[2]), "r"(a[3]), "r"(b0), "r"(b1));
}
__device__ __forceinline__ uint32_t pack_h16(float x, float y) {
    __half2 t = __floats2half2_rn(x, y);
    return *(uint32_t*)&t;
}

// ---------------- fp16 GEMM, B in natural [K,N] layout (trans-ldmatrix) --------
static constexpr uint32_t TA_BYTES = 128 * 80;               // 10240
static constexpr int BSTR = 264;                             // halves (528B)
static constexpr uint32_t TB_BYTES = 32 * BSTR * 2;          // 16896
static constexpr uint32_t TSTAGE = TA_BYTES + TB_BYTES;      // 27136
static constexpr uint32_t TN_SMEM = 4 * TSTAGE;              // 108544

template <bool RELU, bool HALFOUT>
__global__ __launch_bounds__(512, 1) void gemm_tn(
    const __half* __restrict__ A, const __half* __restrict__ B,
    const float* __restrict__ bias, void* __restrict__ Cout, int Nd, int Kd) {
    extern __shared__ char smem[];
    const uint32_t sb = smem_u32(smem);
    const int tid = threadIdx.x;
    const int wid = tid >> 5, lane = tid & 31;
    const int wm = wid & 1, wn = wid >> 1;
    const int bm = blockIdx.x * 128;
    const int bn = blockIdx.y * 256;
    const int NC = Kd >> 5;

    const int arow = tid >> 2, aseg = tid & 3;

    auto issue = [&](int c) {
        const int k0 = c << 5;
        const uint32_t base = sb + (c & 3) * TSTAGE;
        cp16(base + arow * 80 + aseg * 16, A + (size_t)(bm + arow) * Kd + k0 + aseg * 8);
#pragma unroll
        for (int it = 0; it < 2; it++) {
            int i = tid + it * 512;
            int row = i >> 5, seg = i & 31;
            cp16(base + TA_BYTES + row * (BSTR * 2) + seg * 16,
                 B + (size_t)(k0 + row) * Nd + bn + seg * 8);
        }
    };

    issue(0); cp_commit();
    issue(1); cp_commit();
    issue(2); cp_commit();

    float acc[4][4][4];
#pragma unroll
    for (int i = 0; i < 4; i++)
#pragma unroll
        for (int j = 0; j < 4; j++)
#pragma unroll
            for (int r = 0; r < 4; r++) acc[i][j][r] = 0.f;

    const int a_r = lane & 15;
    const int a_c = (lane >> 4) << 3;
    const int tr_r = (lane & 7) + (((lane >> 3) & 1) << 3);
    const int tr_c = (lane >> 4) << 3;

    for (int c = 0; c < NC; c++) {
        cp_wait<2>();
        __syncthreads();
        if (c + 3 < NC) issue(c + 3);
        cp_commit();

        const uint32_t sA = sb + (c & 3) * TSTAGE;
        const uint32_t sB = sA + TA_BYTES;
#pragma unroll
        for (int kk = 0; kk < 2; kk++) {
            uint32_t a[4][4], b[2][4];
#pragma unroll
            for (int mt = 0; mt < 4; mt++)
                ldmat4(a[mt], sA + (uint32_t)(wm * 64 + mt * 16 + a_r) * 80
                              + (uint32_t)(kk * 16 + a_c) * 2);
#pragma unroll
            for (int g = 0; g < 2; g++)
                ldmat4t(b[g], sB + (uint32_t)(kk * 16 + tr_r) * (BSTR * 2)
                              + (uint32_t)(wn * 32 + g * 16 + tr_c) * 2);
#pragma unroll
            for (int mt = 0; mt < 4; mt++)
#pragma unroll
                for (int nt = 0; nt < 4; nt++)
                    mma16816h(acc[mt][nt], a[mt],
                              b[nt >> 1][(nt & 1) * 2], b[nt >> 1][(nt & 1) * 2 + 1]);
        }
    }

    const int g = lane >> 2, t = lane & 3;
#pragma unroll
    for (int mt = 0; mt < 4; mt++) {
#pragma unroll
        for (int nt = 0; nt < 4; nt++) {
            int row0 = bm + wm * 64 + mt * 16 + g;
            int col = bn + wn * 32 + nt * 8 + t * 2;
            float bx = bias[col], by = bias[col + 1];
            float2 v0, v1;
            v0.x = acc[mt][nt][0] + bx; v0.y = acc[mt][nt][1] + by;
            v1.x = acc[mt][nt][2] + bx; v1.y = acc[mt][nt][3] + by;
            if (RELU) {
                v0.x = fmaxf(v0.x, 0.f); v0.y = fmaxf(v0.y, 0.f);
                v1.x = fmaxf(v1.x, 0.f); v1.y = fmaxf(v1.y, 0.f);
            }
            if (HALFOUT) {
                __half* C = (__half*)Cout;
                *(__half2*)&C[(size_t)row0 * Nd + col] = __floats2half2_rn(v0.x, v0.y);
                *(__half2*)&C[(size_t)(row0 + 8) * Nd + col] = __floats2half2_rn(v1.x, v1.y);
            } else {
                float* C = (float*)Cout;
                *(float2*)&C[(size_t)row0 * Nd + col] = v0;
                *(float2*)&C[(size_t)(row0 + 8) * Nd + col] = v1;
            }
        }
    }
}

// ---------------- weight convert fp32 -> fp16 (grid-stride, MLP=4) -------------
__global__ __launch_bounds__(256) void wconv_kernel(
    const float* __restrict__ W, __half* __restrict__ out, int n4) {
    const int stride = gridDim.x * 256;
    int i = blockIdx.x * 256 + threadIdx.x;
    // main loop: 4 independent float4 loads in flight
    for (; i + 3 * stride < n4; i += 4 * stride) {
        float4 v0 = ((const float4*)W)[i];
        float4 v1 = ((const float4*)W)[i + stride];
        float4 v2 = ((const float4*)W)[i + 2 * stride];
        float4 v3 = ((const float4*)W)[i + 3 * stride];
        ((__half2*)out)[(size_t)i * 2]                    = __floats2half2_rn(v0.x, v0.y);
        ((__half2*)out)[(size_t)i * 2 + 1]                = __floats2half2_rn(v0.z, v0.w);
        ((__half2*)out)[((size_t)i + stride) * 2]         = __floats2half2_rn(v1.x, v1.y);
        ((__half2*)out)[((size_t)i + stride) * 2 + 1]     = __floats2half2_rn(v1.z, v1.w);
        ((__half2*)out)[((size_t)i + 2 * stride) * 2]     = __floats2half2_rn(v2.x, v2.y);
        ((__half2*)out)[((size_t)i + 2 * stride) * 2 + 1] = __floats2half2_rn(v2.z, v2.w);
        ((__half2*)out)[((size_t)i + 3 * stride) * 2]     = __floats2half2_rn(v3.x, v3.y);
        ((__half2*)out)[((size_t)i + 3 * stride) * 2 + 1] = __floats2half2_rn(v3.z, v3.w);
    }
    for (; i < n4; i += stride) {
        float4 v = ((const float4*)W)[i];
        ((__half2*)out)[(size_t)i * 2]     = __floats2half2_rn(v.x, v.y);
        ((__half2*)out)[(size_t)i * 2 + 1] = __floats2half2_rn(v.z, v.w);
    }
}

// ---------------- embed + positional encoding -> fp16 --------------------------
__global__ void embed_kernel(const int* __restrict__ x, const float* __restrict__ emb,
                             __half* __restrict__ h16) {
    int row = blockIdx.x;
    int t = row & (cfg::T - 1);
    int tok = x[row];
    const float* e = emb + (size_t)tok * cfg::D;
    int d0 = threadIdx.x * 4;
    float4 ev = *(const float4*)&e[d0];
    const float cfac = -0.017988946039015984f;
    int i0 = d0 >> 1;
    float f0 = expf((float)i0 * cfac);
    float f1 = expf((float)(i0 + 1) * cfac);
    float a0 = (float)t * f0, a1 = (float)t * f1;
    __half2 p0 = __floats2half2_rn(ev.x + sinf(a0), ev.y + cosf(a0));
    __half2 p1 = __floats2half2_rn(ev.z + sinf(a1), ev.w + cosf(a1));
    uint2 pk = make_uint2(*(uint32_t*)&p0, *(uint32_t*)&p1);
    *(uint2*)&h16[(size_t)row * cfg::D + d0] = pk;
}

// ---------------- fp16 flash attention (causal, double-buffered K/V) ----------
static constexpr int FH = 72;

__global__ __launch_bounds__(128) void flash_half(
    const __half* __restrict__ q, const __half* __restrict__ k,
    const __half* __restrict__ v, __half* __restrict__ o16) {
    __shared__ __align__(16) __half sQ[64 * FH];
    __shared__ __align__(16) __half sK[2][64 * FH];
    __shared__ __align__(16) __half sV[2][64 * FH];

    const int qi = gridDim.x - 1 - blockIdx.x;
    const int h = blockIdx.y, b = blockIdx.z;
    const int tid = threadIdx.x;
    const int wid = tid >> 5, lane = tid & 31;
    const size_t headoff = ((size_t)b * cfg::T) * cfg::D + (size_t)h * cfg::HD;

    const uint32_t uQ = smem_u32(sQ);
    const uint32_t uK0 = smem_u32(sK[0]), uV0 = smem_u32(sV[0]);

    const int a_r = lane & 15;
    const int a_c = (lane >> 4) << 3;
    const int b_r = (lane & 7) + ((lane >> 4) << 3);
    const int b_c = ((lane >> 3) & 1) << 3;
    const int kv_r = (lane & 7) + (((lane >> 3) & 1) << 3);
    const int kv_c = (lane >> 4) << 3;
    const int g = lane >> 2, t = lane & 3;

#pragma unroll
    for (int it = 0; it < 4; it++) {
        int idx = tid + it * 128;
        int r = idx >> 3, seg = idx & 7;
        cp16(uQ + r * (FH * 2) + seg * 16,
             q + headoff + (size_t)(qi * 64 + r) * cfg::D + seg * 8);
    }
    cp_commit();

    auto issue_kv = [&](int kt) {
        const int buf = kt & 1;
        const uint32_t uk = uK0 + buf * (64 * FH * 2);
        const uint32_t uv = uV0 + buf * (64 * FH * 2);
#pragma unroll
        for (int it = 0; it < 4; it++) {
            int idx = tid + it * 128;
            int r = idx >> 3, seg = idx & 7;
            size_t go = headoff + (size_t)(kt * 64 + r) * cfg::D + seg * 8;
            cp16(uk + r * (FH * 2) + seg * 16, k + go);
            cp16(uv + r * (FH * 2) + seg * 16, v + go);
        }
    };

    issue_kv(0); cp_commit();

    float accO[8][4];
#pragma unroll
    for (int i = 0; i < 8; i++)
#pragma unroll
        for (int j = 0; j < 4; j++) accO[i][j] = 0.f;
    float m0 = -1e30f, m1 = -1e30f, l0 = 0.f, l1 = 0.f;

    for (int kt = 0; kt <= qi; kt++) {
        cp_wait<0>();
        __syncthreads();
        if (kt < qi) { issue_kv(kt + 1); cp_commit(); }

        const int buf = kt & 1;
        const uint32_t uk = uK0 + buf * (64 * FH * 2);
        const uint32_t uv = uV0 + buf * (64 * FH * 2);

        float sa[8][4];
#pragma unroll
        for (int i = 0; i < 8; i++)
#pragma unroll
            for (int j = 0; j < 4; j++) sa[i][j] = 0.f;
#pragma unroll
        for (int kg = 0; kg < 4; kg++) {
            uint32_t af[4];
            ldmat4(af, uQ + (uint32_t)(wid * 16 + a_r) * (FH * 2) + (kg * 16 + a_c) * 2);
#pragma unroll
            for (int gg = 0; gg < 4; gg++) {
                uint32_t bf[4];
                ldmat4(bf, uk + (uint32_t)(gg * 16 + b_r) * (FH * 2) + (kg * 16 + b_c) * 2);
                mma16816h(sa[gg * 2], af, bf[0], bf[1]);
                mma16816h(sa[gg * 2 + 1], af, bf[2], bf[3]);
            }
        }

        const bool diag = (kt == qi);
#pragma unroll
        for (int nt = 0; nt < 8; nt++) {
            int c0 = nt * 8 + t * 2;
            sa[nt][0] *= 0.125f; sa[nt][1] *= 0.125f;
            sa[nt][2] *= 0.125f; sa[nt][3] *= 0.125f;
            if (diag) {
                int r0 = wid * 16 + g, r1 = r0 + 8;
                if (c0 > r0)     sa[nt][0] = -1e30f;
                if (c0 + 1 > r0) sa[nt][1] = -1e30f;
                if (c0 > r1)     sa[nt][2] = -1e30f;
                if (c0 + 1 > r1) sa[nt][3] = -1e30f;
            }
        }

        float mt0 = -1e30f, mt1 = -1e30f;
#pragma unroll
        for (int nt = 0; nt < 8; nt++) {
            mt0 = fmaxf(mt0, fmaxf(sa[nt][0], sa[nt][1]));
            mt1 = fmaxf(mt1, fmaxf(sa[nt][2], sa[nt][3]));
        }
#pragma unroll
        for (int off = 1; off <= 2; off <<= 1) {
            mt0 = fmaxf(mt0, __shfl_xor_sync(0xffffffffu, mt0, off));
            mt1 = fmaxf(mt1, __shfl_xor_sync(0xffffffffu, mt1, off));
        }
        float mn0 = fmaxf(m0, mt0), mn1 = fmaxf(m1, mt1);
        float al0 = __expf(m0 - mn0), al1 = __expf(m1 - mn1);
        m0 = mn0; m1 = mn1;

        float rs0 = 0.f, rs1 = 0.f;
#pragma unroll
        for (int nt = 0; nt < 8; nt++) {
            sa[nt][0] = __expf(sa[nt][0] - mn0);
            sa[nt][1] = __expf(sa[nt][1] - mn0);
            sa[nt][2] = __expf(sa[nt][2] - mn1);
            sa[nt][3] = __expf(sa[nt][3] - mn1);
            rs0 += sa[nt][0] + sa[nt][1];
            rs1 += sa[nt][2] + sa[nt][3];
        }
#pragma unroll
        for (int off = 1; off <= 2; off <<= 1) {
            rs0 += __shfl_xor_sync(0xffffffffu, rs0, off);
            rs1 += __shfl_xor_sync(0xffffffffu, rs1, off);
        }
        l0 = l0 * al0 + rs0;
        l1 = l1 * al1 + rs1;
#pragma unroll
        for (int nt = 0; nt < 8; nt++) {
            accO[nt][0] *= al0; accO[nt][1] *= al0;
            accO[nt][2] *= al1; accO[nt][3] *= al1;
        }

        uint32_t pf[4][4];
#pragma unroll
        for (int kg = 0; kg < 4; kg++) {
            pf[kg][0] = pack_h16(sa[2 * kg][0],     sa[2 * kg][1]);
            pf[kg][1] = pack_h16(sa[2 * kg][2],     sa[2 * kg][3]);
            pf[kg][2] = pack_h16(sa[2 * kg + 1][0], sa[2 * kg + 1][1]);
            pf[kg][3] = pack_h16(sa[2 * kg + 1][2], sa[2 * kg + 1][3]);
        }

#pragma unroll
        for (int kg = 0; kg < 4; kg++) {
#pragma unroll
            for (int gg = 0; gg < 4; gg++) {
                uint32_t bf[4];
                ldmat4t(bf, uv + (uint32_t)(kg * 16 + kv_r) * (FH * 2) + (gg * 16 + kv_c) * 2);
                mma16816h(accO[gg * 2], pf[kg], bf[0], bf[1]);
                mma16816h(accO[gg * 2 + 1], pf[kg], bf[2], bf[3]);
            }
        }
    }

    float inv0 = 1.0f / l0, inv1 = 1.0f / l1;
    int row0 = qi * 64 + wid * 16 + g;
#pragma unroll
    for (int nt = 0; nt < 8; nt++) {
        int col = nt * 8 + t * 2;
        *(__half2*)&o16[headoff + (size_t)row0 * cfg::D + col] =
            __floats2half2_rn(accO[nt][0] * inv0, accO[nt][1] * inv0);
        *(__half2*)&o16[headoff + (size_t)(row0 + 8) * cfg::D + col] =
            __floats2half2_rn(accO[nt][2] * inv1, accO[nt][3] * inv1);
    }
}

// ---------------- layernorm (unbiased std), fp32 in -> fp16 out ----------------
__inline__ __device__ float block_reduce_sum(float val) {
    __shared__ float sbuf[8];
    int lane = threadIdx.x & 31, wid = threadIdx.x >> 5;
#pragma unroll
    for (int o = 16; o; o >>= 1) val += __shfl_xor_sync(0xffffffffu, val, o);
    if (lane == 0) sbuf[wid] = val;
    __syncthreads();
    val = (threadIdx.x < 8) ? sbuf[threadIdx.x] : 0.f;
    if (wid == 0) {
#pragma unroll
        for (int o = 4; o; o >>= 1) val += __shfl_xor_sync(0xffffffffu, val, o);
        if (lane == 0) sbuf[0] = val;
    }
    __syncthreads();
    float r = sbuf[0];
    __syncthreads();
    return r;
}

__global__ void layernorm_kernel(const float* __restrict__ in, __half* __restrict__ out16,
                                 const float* __restrict__ g, const float* __restrict__ be) {
    int row = blockIdx.x;
    const float* p = in + (size_t)row * cfg::D;
    int d0 = threadIdx.x * 4;
    float4 xv = *(const float4*)&p[d0];
    float s = xv.x + xv.y + xv.z + xv.w;
    s = block_reduce_sum(s);
    float mean = s * (1.0f / cfg::D);
    float dx[4] = {xv.x - mean, xv.y - mean, xv.z - mean, xv.w - mean};
    float sq = dx[0] * dx[0] + dx[1] * dx[1] + dx[2] * dx[2] + dx[3] * dx[3];
    sq = block_reduce_sum(sq);
    float stdv = sqrtf(sq / (float)(cfg::D - 1));
    float inv = 1.0f / (stdv + cfg::EPS);
    float4 gg = *(const float4*)&g[d0];
    float4 bb = *(const float4*)&be[d0];
    __half2 p0 = __floats2half2_rn(dx[0] * inv * gg.x + bb.x, dx[1] * inv * gg.y + bb.y);
    __half2 p1 = __floats2half2_rn(dx[2] * inv * gg.z + bb.z, dx[3] * inv * gg.w + bb.w);
    uint2 pk = make_uint2(*(uint32_t*)&p0, *(uint32_t*)&p1);
    *(uint2*)&out16[(size_t)row * cfg::D + d0] = pk;
}

// ---------------- row softmax over V=32000 -------------------------------------
__global__ void softmax_kernel(float* __restrict__ out) {
    int row = blockIdx.x;
    float* p = out + (size_t)row * cfg::V;
    float m = -1e30f, s = 0.f;
    for (int j = threadIdx.x; j < cfg::V; j += 256) {
        float xv = p[j];
        if (xv > m) { s = s * __expf(m - xv) + 1.0f; m = xv; }
        else        { s += __expf(xv - m); }
    }
    __shared__ float sm[256], ss[256];
    sm[threadIdx.x] = m; ss[threadIdx.x] = s;
    __syncthreads();
    for (int off = 128; off; off >>= 1) {
        if (threadIdx.x < off) {
            float m1 = sm[threadIdx.x], s1 = ss[threadIdx.x];
            float m2 = sm[threadIdx.x + off], s2 = ss[threadIdx.x + off];
            float mm = fmaxf(m1, m2);
            sm[threadIdx.x] = mm;
            ss[threadIdx.x] = s1 * __expf(m1 - mm) + s2 * __expf(m2 - mm);
        }
        __syncthreads();
    }
    float mall = sm[0];
    float inv = 1.0f / ss[0];
    for (int j = threadIdx.x; j < cfg::V; j += 256) {
        p[j] = __expf(p[j] - mall) * inv;
    }
}

// ---------------- host orchestration -------------------------------------------
extern "C" void kernel_launch(void* const* d_in, const int* in_sizes, int n_in,
                              void* d_out, int out_size) {
    using namespace cfg;
    const int*   x   = (const int*)d_in[0];
    const float* emb = (const float*)d_in[1];
    const float* Wq  = (const float*)d_in[2];
    const float* bq  = (const float*)d_in[3];
    const float* Wk  = (const float*)d_in[4];
    const float* bk  = (const float*)d_in[5];
    const float* Wv  = (const float*)d_in[6];
    const float* bv  = (const float*)d_in[7];
    const float* Wo  = (const float*)d_in[8];
    const float* bo  = (const float*)d_in[9];
    const float* g1  = (const float*)d_in[10];
    const float* be1 = (const float*)d_in[11];
    const float* W1  = (const float*)d_in[12];
    const float* bf1 = (const float*)d_in[13];
    const float* W2  = (const float*)d_in[14];
    const float* bf2 = (const float*)d_in[15];
    const float* g2  = (const float*)d_in[16];
    const float* be2 = (const float*)d_in[17];
    const float* Wl  = (const float*)d_in[18];
    const float* bl  = (const float*)d_in[19];
    float* out = (float*)d_out;

    float *h, *o;
    cudaGetSymbolAddress((void**)&h, g_h);
    cudaGetSymbolAddress((void**)&o, g_o);

    __half *x16, *h16, *o16, *q16, *k16, *v16, *wq, *wk, *wv, *wo, *w1, *w2, *wl;
    cudaGetSymbolAddress((void**)&x16, g_x16);
    cudaGetSymbolAddress((void**)&h16, g_h16);
    cudaGetSymbolAddress((void**)&o16, g_o16);
    cudaGetSymbolAddress((void**)&q16, g_q16);
    cudaGetSymbolAddress((void**)&k16, g_k16);
    cudaGetSymbolAddress((void**)&v16, g_v16);
    cudaGetSymbolAddress((void**)&wq, g_wq);
    cudaGetSymbolAddress((void**)&wk, g_wk);
    cudaGetSymbolAddress((void**)&wv, g_wv);
    cudaGetSymbolAddress((void**)&wo, g_wo);
    cudaGetSymbolAddress((void**)&w1, g_w1);
    cudaGetSymbolAddress((void**)&w2, g_w2);
    cudaGetSymbolAddress((void**)&wl, g_wl);

    cudaFuncSetAttribute((const void*)gemm_tn<false, false>,
                         cudaFuncAttributeMaxDynamicSharedMemorySize, TN_SMEM);
    cudaFuncSetAttribute((const void*)gemm_tn<true, true>,
                         cudaFuncAttributeMaxDynamicSharedMemorySize, TN_SMEM);
    cudaFuncSetAttribute((const void*)gemm_tn<false, true>,
                         cudaFuncAttributeMaxDynamicSharedMemorySize, TN_SMEM);

    const int WG = 1184;   // 8 CTAs/SM worth of grid for grid-stride wconv
    embed_kernel<<<M, 256>>>(x, emb, h16);
    wconv_kernel<<<WG, 256>>>(Wq, wq, D * D / 4);
    wconv_kernel<<<WG, 256>>>(Wk, wk, D * D / 4);
    wconv_kernel<<<WG, 256>>>(Wv, wv, D * D / 4);
    wconv_kernel<<<WG, 256>>>(Wo, wo, D * D / 4);
    gemm_tn<false, true><<<dim3(M / 128, D / 256), 512, TN_SMEM>>>(h16, wq, bq, q16, D, D);
    gemm_tn<false, true><<<dim3(M / 128, D / 256), 512, TN_SMEM>>>(h16, wk, bk, k16, D, D);
    gemm_tn<false, true><<<dim3(M / 128, D / 256), 512, TN_SMEM>>>(h16, wv, bv, v16, D, D);

    flash_half<<<dim3(T / 64, H, B), 128>>>(q16, k16, v16, o16);

    gemm_tn<false, false><<<dim3(M / 128, D / 256), 512, TN_SMEM>>>(o16, wo, bo, h, D, D);
    layernorm_kernel<<<M, 256>>>(h, h16, g1, be1);

    wconv_kernel<<<WG, 256>>>(W1, w1, D * F / 4);
    gemm_tn<true, true><<<dim3(M / 128, F / 256), 512, TN_SMEM>>>(h16, w1, bf1, x16, F, D);

    wconv_kernel<<<WG, 256>>>(W2, w2, D * F / 4);
    gemm_tn<false, false><<<dim3(M / 128, D / 256), 512, TN_SMEM>>>(x16, w2, bf2, o, D, F);
    layernorm_kernel<<<M, 256>>>(o, o16, g2, be2);

    wconv_kernel<<<WG, 256>>>(Wl, wl, (int)((size_t)D * V / 4));
    gemm_tn<false, false><<<dim3(M / 128, V / 256), 512, TN_SMEM>>>(o16, wl, bl, out, V, D);

    softmax_kernel<<<M, 256>>>(out);
}